// round 13
// baseline (speedup 1.0000x reference)
#include <cuda_runtime.h>
#include <cuda_fp16.h>
#include <cstdint>

// ---------------- problem constants ----------------
#define BB 4
#define LL 2048
#define DD 2048
#define SS 16
#define KK 4
#define NB 2
#define HH 32
#define HD 64
#define EPSF 1e-6f

// ---------------- device scratch (no allocs allowed) ----------------
__device__ float g_x[BB * LL * DD];
__device__ float g_xb[BB * LL * DD];
__device__ float g_logits[BB * LL * SS];
__device__ float g_ws[BB * SS * DD];
__device__ float g_kv[BB * SS * 2 * DD];
__device__ float g_part[8 * 64 * 4096];       // split-K partials
__device__ float g_wgt[BB * SS * KK];
__device__ float g_sbias[BB * HH * SS];
__device__ int   g_idx[BB * SS * KK];

// fp16 hi/lo split operand buffers
__device__ __half g_xh[BB * LL * DD],  g_xl[BB * LL * DD];
__device__ __half g_wkvh[2 * DD * DD],  g_wkvl[2 * DD * DD];
__device__ __half g_wwh[DD * DD],       g_wwl[DD * DD];
__device__ __half g_Gh[BB * HH * SS * DD], g_Gl[BB * HH * SS * DD];
__device__ __half g_atth[BB * LL * HH * SS];
__device__ __half g_voTh[BB * DD * HH * SS], g_voTl[BB * DD * HH * SS];
__device__ __half g_wsh[BB * SS * DD],  g_wsl[BB * SS * DD];
__device__ __half g_xwh[BB * SS * DD],  g_xwl[BB * SS * DD];

// ---------------- PTX helpers ----------------
__device__ __forceinline__ void cp16(void* sdst, const void* gsrc) {
    uint32_t d = (uint32_t)__cvta_generic_to_shared(sdst);
    asm volatile("cp.async.cg.shared.global [%0], [%1], 16;\n" :: "r"(d), "l"(gsrc));
}
__device__ __forceinline__ void cp_commit() { asm volatile("cp.async.commit_group;\n"); }
template <int N> __device__ __forceinline__ void cp_wait() {
    asm volatile("cp.async.wait_group %0;\n" :: "n"(N));
}
__device__ __forceinline__ void ldsm4(uint32_t* r, uint32_t saddr) {
    asm volatile("ldmatrix.sync.aligned.m8n8.x4.shared.b16 {%0,%1,%2,%3}, [%4];\n"
                 : "=r"(r[0]), "=r"(r[1]), "=r"(r[2]), "=r"(r[3]) : "r"(saddr));
}
__device__ __forceinline__ void mma_f32(float* c, const uint32_t* a, uint32_t b0, uint32_t b1) {
    asm volatile("mma.sync.aligned.m16n8k16.row.col.f32.f16.f16.f32 "
                 "{%0,%1,%2,%3}, {%4,%5,%6,%7}, {%8,%9}, {%0,%1,%2,%3};\n"
                 : "+f"(c[0]), "+f"(c[1]), "+f"(c[2]), "+f"(c[3])
                 : "r"(a[0]), "r"(a[1]), "r"(a[2]), "r"(a[3]), "r"(b0), "r"(b1));
}
__device__ __forceinline__ void mma_f16(uint32_t* c, const uint32_t* a, uint32_t b0, uint32_t b1) {
    asm volatile("mma.sync.aligned.m16n8k16.row.col.f16.f16.f16.f16 "
                 "{%0,%1}, {%2,%3,%4,%5}, {%6,%7}, {%0,%1};\n"
                 : "+r"(c[0]), "+r"(c[1])
                 : "r"(a[0]), "r"(a[1]), "r"(a[2]), "r"(a[3]), "r"(b0), "r"(b1));
}
__device__ __forceinline__ void split1(float v, __half& h, __half& l) {
    h = __float2half_rn(v);
    l = __float2half_rn(v - __half2float(h));
}
__device__ __forceinline__ uint32_t smem_u32(const void* p) {
    return (uint32_t)__cvta_generic_to_shared(p);
}
__device__ __forceinline__ void fold_hc(float* c, const uint32_t* hc) {
    __half2 p0 = *reinterpret_cast<const __half2*>(&hc[0]);
    __half2 p1 = *reinterpret_cast<const __half2*>(&hc[1]);
    c[0] += __low2float(p0); c[1] += __high2float(p0);
    c[2] += __low2float(p1); c[3] += __high2float(p1);
}

// ---------------- splits ----------------
__global__ void split4_kernel(const float* __restrict__ src, __half* __restrict__ hi,
                              __half* __restrict__ lo, long n4) {
    long i = (long)blockIdx.x * blockDim.x + threadIdx.x;
    if (i >= n4) return;
    float4 v = ((const float4*)src)[i];
    __half h[4], l[4];
    split1(v.x, h[0], l[0]); split1(v.y, h[1], l[1]);
    split1(v.z, h[2], l[2]); split1(v.w, h[3], l[3]);
    ((__half2*)hi)[2 * i]     = __halves2half2(h[0], h[1]);
    ((__half2*)hi)[2 * i + 1] = __halves2half2(h[2], h[3]);
    ((__half2*)lo)[2 * i]     = __halves2half2(l[0], l[1]);
    ((__half2*)lo)[2 * i + 1] = __halves2half2(l[2], l[3]);
}

__global__ void copysplit_kernel(const float* __restrict__ src, float* __restrict__ dst,
                                 __half* __restrict__ hi, __half* __restrict__ lo, long n4) {
    long i = (long)blockIdx.x * blockDim.x + threadIdx.x;
    if (i >= n4) return;
    float4 v = ((const float4*)src)[i];
    ((float4*)dst)[i] = v;
    __half h[4], l[4];
    split1(v.x, h[0], l[0]); split1(v.y, h[1], l[1]);
    split1(v.z, h[2], l[2]); split1(v.w, h[3], l[3]);
    ((__half2*)hi)[2 * i]     = __halves2half2(h[0], h[1]);
    ((__half2*)hi)[2 * i + 1] = __halves2half2(h[2], h[3]);
    ((__half2*)lo)[2 * i]     = __halves2half2(l[0], l[1]);
    ((__half2*)lo)[2 * i + 1] = __halves2half2(l[2], l[3]);
}

__global__ void init_ws_kernel(const float* __restrict__ wsrc, float* __restrict__ ws) {
    int bs = blockIdx.x;
    int s = bs % SS;
    for (int d = threadIdx.x; d < DD; d += blockDim.x)
        ws[(long)bs * DD + d] = wsrc[(long)s * DD + d];
}

// ---------------- 2-term GEMM for xb: C = A @ (Bh+Bl)^T + bias ----------------
// A single fp16 (att); hh in f32 acc, h*lo in fp16 acc chained across K.
__global__ __launch_bounds__(256) void gemm2_kernel(
    const __half* __restrict__ A,
    const __half* __restrict__ Bh, const __half* __restrict__ Bl,
    const float* __restrict__ bias, float* __restrict__ C,
    int M, int N, int K, long bsA, long bsB, long bsC) {
    A  += (long)blockIdx.z * bsA;
    Bh += (long)blockIdx.z * bsB; Bl += (long)blockIdx.z * bsB;
    C  += (long)blockIdx.z * bsC;

    __shared__ __align__(16) __half sm[2][3][128 * 24];

    const int tid = threadIdx.x;
    const int m0 = blockIdx.y * 128, n0 = blockIdx.x * 128;

    const int lrow = tid >> 1, lhalf = tid & 1;
    int arow = m0 + lrow; if (arow >= M) arow = M - 1;
    int brow = n0 + lrow; if (brow >= N) brow = N - 1;
    const long aoff = (long)arow * K + lhalf * 8;
    const long boff = (long)brow * K + lhalf * 8;
    const uint32_t soff = lrow * 24 + lhalf * 8;

    const int NT = K >> 4;

    cp16(&sm[0][0][soff], A + aoff);
    cp16(&sm[0][1][soff], Bh + boff);
    cp16(&sm[0][2][soff], Bl + boff);
    cp_commit();

    const int lane = tid & 31, warp = tid >> 5;
    const int wm = (warp & 3) * 32;
    const int wn = (warp >> 2) * 64;

    uint32_t a_row = wm + (lane & 7) + ((lane >> 3) & 1) * 8;
    uint32_t a_k   = (lane >> 4) * 8;
    uint32_t aoffs[2];
    aoffs[0] = ((a_row) * 24 + a_k) * 2;
    aoffs[1] = ((a_row + 16) * 24 + a_k) * 2;
    uint32_t b_row = wn + (lane & 7) + ((lane >> 4) ? 8 : 0);
    uint32_t b_k   = ((lane >> 3) & 1) * 8;
    uint32_t boffs[4];
#pragma unroll
    for (int p = 0; p < 4; p++) boffs[p] = ((b_row + p * 16) * 24 + b_k) * 2;

    const uint32_t smbase = smem_u32(&sm[0][0][0]);
    const uint32_t ARR = 128 * 24 * 2;

    float acc[2][8][4];
    uint32_t hc[2][8][2];
#pragma unroll
    for (int mt = 0; mt < 2; mt++)
#pragma unroll
        for (int nt = 0; nt < 8; nt++) {
#pragma unroll
            for (int j = 0; j < 4; j++) acc[mt][nt][j] = 0.f;
            hc[mt][nt][0] = 0u; hc[mt][nt][1] = 0u;
        }

    for (int kt = 0; kt < NT; kt++) {
        const int cur = kt & 1;
        if (kt + 1 < NT) {
            const int nx = cur ^ 1;
            const long kb = (long)(kt + 1) << 4;
            cp16(&sm[nx][0][soff], A + aoff + kb);
            cp16(&sm[nx][1][soff], Bh + boff + kb);
            cp16(&sm[nx][2][soff], Bl + boff + kb);
            cp_commit();
            cp_wait<1>();
        } else {
            cp_wait<0>();
        }
        __syncthreads();

        const uint32_t bA  = smbase + (cur * 3 + 0) * ARR;
        const uint32_t bBh = smbase + (cur * 3 + 1) * ARR;
        const uint32_t bBl = smbase + (cur * 3 + 2) * ARR;

        uint32_t ah[2][4], bh[4][4], bl[4][4];
#pragma unroll
        for (int mt = 0; mt < 2; mt++) ldsm4(ah[mt], bA + aoffs[mt]);
#pragma unroll
        for (int p = 0; p < 4; p++) {
            ldsm4(bh[p], bBh + boffs[p]);
            ldsm4(bl[p], bBl + boffs[p]);
        }

#pragma unroll
        for (int mt = 0; mt < 2; mt++)
#pragma unroll
            for (int nt = 0; nt < 8; nt++)
                mma_f32(acc[mt][nt], ah[mt],
                        bh[nt >> 1][(nt & 1) * 2], bh[nt >> 1][(nt & 1) * 2 + 1]);
#pragma unroll
        for (int mt = 0; mt < 2; mt++)
#pragma unroll
            for (int nt = 0; nt < 8; nt++)
                mma_f16(hc[mt][nt], ah[mt],
                        bl[nt >> 1][(nt & 1) * 2], bl[nt >> 1][(nt & 1) * 2 + 1]);
        __syncthreads();
    }

#pragma unroll
    for (int mt = 0; mt < 2; mt++) {
        int r0 = m0 + wm + mt * 16 + (lane >> 2);
#pragma unroll
        for (int nt = 0; nt < 8; nt++) {
            fold_hc(acc[mt][nt], hc[mt][nt]);
            int cc = n0 + wn + nt * 8 + (lane & 3) * 2;
            float b0v = bias[cc], b1v = bias[cc + 1];
            float* c = acc[mt][nt];
            if (r0 < M) {
                float2 o; o.x = c[0] + b0v; o.y = c[1] + b1v;
                *(float2*)(C + (long)r0 * N + cc) = o;
            }
            if (r0 + 8 < M) {
                float2 o; o.x = c[2] + b0v; o.y = c[3] + b1v;
                *(float2*)(C + (long)(r0 + 8) * N + cc) = o;
            }
        }
    }
}

// ---------------- scores GEMM (3-term, chained lo acc) + fused softmax ----------------
__global__ __launch_bounds__(256) void gemm3s_kernel(
    const __half* __restrict__ Ah, const __half* __restrict__ Al,
    const __half* __restrict__ Bh, const __half* __restrict__ Bl,
    const float* __restrict__ sbias,
    __half* __restrict__ atth,
    int K, long bsA, long bsB) {
    const int b = blockIdx.z;
    Ah += (long)b * bsA; Al += (long)b * bsA;
    Bh += (long)b * bsB; Bl += (long)b * bsB;
    const float* sb = sbias + (long)b * (HH * SS);

    __shared__ __align__(16) __half sm[2][4][128 * 24];

    const int tid = threadIdx.x;
    const int m0 = blockIdx.y * 128, n0 = blockIdx.x * 128;

    const int lrow = tid >> 1, lhalf = tid & 1;
    const long aoff = (long)(m0 + lrow) * K + lhalf * 8;
    const long boff = (long)(n0 + lrow) * K + lhalf * 8;
    const uint32_t soff = lrow * 24 + lhalf * 8;

    const int NT = K >> 4;

    cp16(&sm[0][0][soff], Ah + aoff);
    cp16(&sm[0][1][soff], Al + aoff);
    cp16(&sm[0][2][soff], Bh + boff);
    cp16(&sm[0][3][soff], Bl + boff);
    cp_commit();

    const int lane = tid & 31, warp = tid >> 5;
    const int wm = (warp & 3) * 32;
    const int wn = (warp >> 2) * 64;

    uint32_t a_row = wm + (lane & 7) + ((lane >> 3) & 1) * 8;
    uint32_t a_k   = (lane >> 4) * 8;
    uint32_t aoffs[2];
    aoffs[0] = ((a_row) * 24 + a_k) * 2;
    aoffs[1] = ((a_row + 16) * 24 + a_k) * 2;
    uint32_t b_row = wn + (lane & 7) + ((lane >> 4) ? 8 : 0);
    uint32_t b_k   = ((lane >> 3) & 1) * 8;
    uint32_t boffs[4];
#pragma unroll
    for (int p = 0; p < 4; p++) boffs[p] = ((b_row + p * 16) * 24 + b_k) * 2;

    const uint32_t smbase = smem_u32(&sm[0][0][0]);
    const uint32_t ARR = 128 * 24 * 2;

    float acc[2][8][4];
    uint32_t hc[2][8][2];
#pragma unroll
    for (int mt = 0; mt < 2; mt++)
#pragma unroll
        for (int nt = 0; nt < 8; nt++) {
#pragma unroll
            for (int j = 0; j < 4; j++) acc[mt][nt][j] = 0.f;
            hc[mt][nt][0] = 0u; hc[mt][nt][1] = 0u;
        }

    for (int kt = 0; kt < NT; kt++) {
        const int cur = kt & 1;
        if (kt + 1 < NT) {
            const int nx = cur ^ 1;
            const long kb = (long)(kt + 1) << 4;
            cp16(&sm[nx][0][soff], Ah + aoff + kb);
            cp16(&sm[nx][1][soff], Al + aoff + kb);
            cp16(&sm[nx][2][soff], Bh + boff + kb);
            cp16(&sm[nx][3][soff], Bl + boff + kb);
            cp_commit();
            cp_wait<1>();
        } else {
            cp_wait<0>();
        }
        __syncthreads();

        const uint32_t bAh = smbase + (cur * 4 + 0) * ARR;
        const uint32_t bAl = smbase + (cur * 4 + 1) * ARR;
        const uint32_t bBh = smbase + (cur * 4 + 2) * ARR;
        const uint32_t bBl = smbase + (cur * 4 + 3) * ARR;

        uint32_t ah[2][4], al[2][4], bh[4][4], bl[4][4];
#pragma unroll
        for (int mt = 0; mt < 2; mt++) {
            ldsm4(ah[mt], bAh + aoffs[mt]);
            ldsm4(al[mt], bAl + aoffs[mt]);
        }
#pragma unroll
        for (int p = 0; p < 4; p++) {
            ldsm4(bh[p], bBh + boffs[p]);
            ldsm4(bl[p], bBl + boffs[p]);
        }

#pragma unroll
        for (int mt = 0; mt < 2; mt++)
#pragma unroll
            for (int nt = 0; nt < 8; nt++)
                mma_f32(acc[mt][nt], ah[mt],
                        bh[nt >> 1][(nt & 1) * 2], bh[nt >> 1][(nt & 1) * 2 + 1]);
#pragma unroll
        for (int mt = 0; mt < 2; mt++)
#pragma unroll
            for (int nt = 0; nt < 8; nt++) {
                mma_f16(hc[mt][nt], ah[mt],
                        bl[nt >> 1][(nt & 1) * 2], bl[nt >> 1][(nt & 1) * 2 + 1]);
                mma_f16(hc[mt][nt], al[mt],
                        bh[nt >> 1][(nt & 1) * 2], bh[nt >> 1][(nt & 1) * 2 + 1]);
            }
        __syncthreads();
    }

#pragma unroll
    for (int mt = 0; mt < 2; mt++)
#pragma unroll
        for (int nt = 0; nt < 8; nt++) fold_hc(acc[mt][nt], hc[mt][nt]);

    // fused softmax epilogue over 16-col head groups (quad shfl)
#pragma unroll
    for (int mt = 0; mt < 2; mt++) {
        int r0 = m0 + wm + mt * 16 + (lane >> 2);
#pragma unroll
        for (int half = 0; half < 2; half++) {
            int row = r0 + half * 8;
            long obase = ((long)b * LL + row) * (HH * SS) + n0;
#pragma unroll
            for (int g = 0; g < 4; g++) {
                int c0 = wn + (2 * g) * 8 + (lane & 3) * 2;
                int c1 = wn + (2 * g + 1) * 8 + (lane & 3) * 2;
                float x0 = (acc[mt][2 * g][half * 2 + 0]     + sb[n0 + c0])     * 0.125f;
                float x1 = (acc[mt][2 * g][half * 2 + 1]     + sb[n0 + c0 + 1]) * 0.125f;
                float x2 = (acc[mt][2 * g + 1][half * 2 + 0] + sb[n0 + c1])     * 0.125f;
                float x3 = (acc[mt][2 * g + 1][half * 2 + 1] + sb[n0 + c1 + 1]) * 0.125f;
                float mx = fmaxf(fmaxf(x0, x1), fmaxf(x2, x3));
                mx = fmaxf(mx, __shfl_xor_sync(0xffffffffu, mx, 1));
                mx = fmaxf(mx, __shfl_xor_sync(0xffffffffu, mx, 2));
                float e0 = expf(x0 - mx), e1 = expf(x1 - mx);
                float e2 = expf(x2 - mx), e3 = expf(x3 - mx);
                float s = e0 + e1 + e2 + e3;
                s += __shfl_xor_sync(0xffffffffu, s, 1);
                s += __shfl_xor_sync(0xffffffffu, s, 2);
                float inv = 1.f / s;
                *(__half2*)(atth + obase + c0) =
                    __halves2half2(__float2half_rn(e0 * inv), __float2half_rn(e1 * inv));
                *(__half2*)(atth + obase + c1) =
                    __halves2half2(__float2half_rn(e2 * inv), __float2half_rn(e3 * inv));
            }
        }
    }
}

// ---------------- split-K 3-term GEMM: partial C (no bias) ----------------
__global__ __launch_bounds__(256) void gemm3p_kernel(
    const __half* __restrict__ Ah, const __half* __restrict__ Al,
    const __half* __restrict__ Bh, const __half* __restrict__ Bl,
    float* __restrict__ P, int M, int N, int K, int kLen) {
    const int ksplit = blockIdx.z;
    const int k0base = ksplit * kLen;
    P += (long)ksplit * M * N;

    __shared__ __align__(16) __half sm[2][4][128 * 24];

    const int tid = threadIdx.x;
    const int m0 = blockIdx.y * 128, n0 = blockIdx.x * 128;

    const int lrow = tid >> 1, lhalf = tid & 1;
    int arow = m0 + lrow; if (arow >= M) arow = M - 1;
    int brow = n0 + lrow; if (brow >= N) brow = N - 1;
    const long aoff = (long)arow * K + k0base + lhalf * 8;
    const long boff = (long)brow * K + k0base + lhalf * 8;
    const uint32_t soff = lrow * 24 + lhalf * 8;

    const int NT = kLen >> 4;

    cp16(&sm[0][0][soff], Ah + aoff);
    cp16(&sm[0][1][soff], Al + aoff);
    cp16(&sm[0][2][soff], Bh + boff);
    cp16(&sm[0][3][soff], Bl + boff);
    cp_commit();

    const int lane = tid & 31, warp = tid >> 5;
    const int wm = (warp & 3) * 32;
    const int wn = (warp >> 2) * 64;

    uint32_t a_row = wm + (lane & 7) + ((lane >> 3) & 1) * 8;
    uint32_t a_k   = (lane >> 4) * 8;
    uint32_t aoffs[2];
    aoffs[0] = ((a_row) * 24 + a_k) * 2;
    aoffs[1] = ((a_row + 16) * 24 + a_k) * 2;
    uint32_t b_row = wn + (lane & 7) + ((lane >> 4) ? 8 : 0);
    uint32_t b_k   = ((lane >> 3) & 1) * 8;
    uint32_t boffs[4];
#pragma unroll
    for (int p = 0; p < 4; p++) boffs[p] = ((b_row + p * 16) * 24 + b_k) * 2;

    const uint32_t smbase = smem_u32(&sm[0][0][0]);
    const uint32_t ARR = 128 * 24 * 2;

    float acc[2][8][4];
    uint32_t hc[2][8][2];
#pragma unroll
    for (int mt = 0; mt < 2; mt++)
#pragma unroll
        for (int nt = 0; nt < 8; nt++) {
#pragma unroll
            for (int j = 0; j < 4; j++) acc[mt][nt][j] = 0.f;
            hc[mt][nt][0] = 0u; hc[mt][nt][1] = 0u;
        }

    for (int kt = 0; kt < NT; kt++) {
        const int cur = kt & 1;
        if (kt + 1 < NT) {
            const int nx = cur ^ 1;
            const long kb = (long)(kt + 1) << 4;
            cp16(&sm[nx][0][soff], Ah + aoff + kb);
            cp16(&sm[nx][1][soff], Al + aoff + kb);
            cp16(&sm[nx][2][soff], Bh + boff + kb);
            cp16(&sm[nx][3][soff], Bl + boff + kb);
            cp_commit();
            cp_wait<1>();
        } else {
            cp_wait<0>();
        }
        __syncthreads();

        const uint32_t bAh = smbase + (cur * 4 + 0) * ARR;
        const uint32_t bAl = smbase + (cur * 4 + 1) * ARR;
        const uint32_t bBh = smbase + (cur * 4 + 2) * ARR;
        const uint32_t bBl = smbase + (cur * 4 + 3) * ARR;

        uint32_t ah[2][4], al[2][4], bh[4][4], bl[4][4];
#pragma unroll
        for (int mt = 0; mt < 2; mt++) {
            ldsm4(ah[mt], bAh + aoffs[mt]);
            ldsm4(al[mt], bAl + aoffs[mt]);
        }
#pragma unroll
        for (int p = 0; p < 4; p++) {
            ldsm4(bh[p], bBh + boffs[p]);
            ldsm4(bl[p], bBl + boffs[p]);
        }

#pragma unroll
        for (int mt = 0; mt < 2; mt++)
#pragma unroll
            for (int nt = 0; nt < 8; nt++)
                mma_f32(acc[mt][nt], ah[mt],
                        bh[nt >> 1][(nt & 1) * 2], bh[nt >> 1][(nt & 1) * 2 + 1]);
#pragma unroll
        for (int mt = 0; mt < 2; mt++)
#pragma unroll
            for (int nt = 0; nt < 8; nt++) {
                mma_f16(hc[mt][nt], ah[mt],
                        bl[nt >> 1][(nt & 1) * 2], bl[nt >> 1][(nt & 1) * 2 + 1]);
                mma_f16(hc[mt][nt], al[mt],
                        bh[nt >> 1][(nt & 1) * 2], bh[nt >> 1][(nt & 1) * 2 + 1]);
            }
        __syncthreads();
    }

#pragma unroll
    for (int mt = 0; mt < 2; mt++) {
        int r0 = m0 + wm + mt * 16 + (lane >> 2);
#pragma unroll
        for (int nt = 0; nt < 8; nt++) {
            fold_hc(acc[mt][nt], hc[mt][nt]);
            int cc = n0 + wn + nt * 8 + (lane & 3) * 2;
            float* c = acc[mt][nt];
            if (r0 < M) {
                float2 o; o.x = c[0]; o.y = c[1];
                *(float2*)(P + (long)r0 * N + cc) = o;
            }
            if (r0 + 8 < M) {
                float2 o; o.x = c[2]; o.y = c[3];
                *(float2*)(P + (long)(r0 + 8) * N + cc) = o;
            }
        }
    }
}

// ---------------- kv reduce ----------------
__global__ void kvred_kernel(const float* __restrict__ P, const float* __restrict__ bias,
                             float* __restrict__ out) {
    int i4 = blockIdx.x * 256 + threadIdx.x;
    if (i4 >= 65536) return;
    const float4* P4 = (const float4*)P;
    float4 a = P4[i4];
#pragma unroll
    for (int s = 1; s < 8; s++) {
        float4 b = P4[s * 65536 + i4];
        a.x += b.x; a.y += b.y; a.z += b.z; a.w += b.w;
    }
    int n = (i4 * 4) & 4095;
    const float4 bv = *(const float4*)(bias + n);
    a.x += bv.x; a.y += bv.y; a.z += bv.z; a.w += bv.w;
    ((float4*)out)[i4] = a;
}

// ---------------- compete logits: cw staged in dynamic smem ----------------
__global__ void compete_kernel(const float* __restrict__ x, const float* __restrict__ cw,
                               const float* __restrict__ cb, const float* __restrict__ npw,
                               float* __restrict__ logits) {
    extern __shared__ float scw[];
    int tid = threadIdx.x;
    for (int e = tid; e < SS * DD; e += 512) scw[e] = cw[e];
    __syncthreads();
    int warp = tid >> 5, lane = tid & 31;
#pragma unroll
    for (int r = 0; r < 2; r++) {
        int row = blockIdx.x * 32 + warp * 2 + r;
        const float* xr = x + (long)row * DD;
        float ss = 0.f;
        float acc[SS];
#pragma unroll
        for (int s = 0; s < SS; s++) acc[s] = 0.f;
        for (int j = lane; j < DD; j += 32) {
            float xv = xr[j];
            ss += xv * xv;
            float xn = xv * npw[j];
#pragma unroll
            for (int s = 0; s < SS; s++) acc[s] += xn * scw[s * DD + j];
        }
#pragma unroll
        for (int o = 16; o; o >>= 1) ss += __shfl_xor_sync(0xffffffffu, ss, o);
#pragma unroll
        for (int s = 0; s < SS; s++) {
#pragma unroll
            for (int o = 16; o; o >>= 1) acc[s] += __shfl_xor_sync(0xffffffffu, acc[s], o);
        }
        float rinv = rsqrtf(ss * (1.f / DD) + EPSF);
        float myv = 0.f;
#pragma unroll
        for (int s = 0; s < SS; s++) if (lane == s) myv = acc[s];
        if (lane < SS) logits[(long)row * SS + lane] = myv * rinv + cb[lane];
    }
}

// ---------------- top-4 + softmax weights (tree merge) ----------------
__device__ __forceinline__ bool tk_better(float v1, int i1, float v2, int i2) {
    return (v1 > v2) || (v1 == v2 && i1 < i2);
}
__device__ __forceinline__ void tk_insert(float* v, int* id, float nv, int ni) {
    if (tk_better(nv, ni, v[KK - 1], id[KK - 1])) {
        v[KK - 1] = nv; id[KK - 1] = ni;
#pragma unroll
        for (int j = KK - 1; j > 0; j--) {
            if (tk_better(v[j], id[j], v[j - 1], id[j - 1])) {
                float tv = v[j]; v[j] = v[j - 1]; v[j - 1] = tv;
                int ti = id[j]; id[j] = id[j - 1]; id[j - 1] = ti;
            }
        }
    }
}

__global__ void topk_kernel(const float* __restrict__ logits, int* __restrict__ idxo,
                            float* __restrict__ wgto) {
    int bs = blockIdx.x;
    int b = bs / SS, s = bs % SS;
    int tid = threadIdx.x;
    float v[KK]; int id[KK];
#pragma unroll
    for (int k = 0; k < KK; k++) { v[k] = -3.4e38f; id[k] = 0x7fffffff; }
    for (int l = tid; l < LL; l += 256)
        tk_insert(v, id, logits[((long)b * LL + l) * SS + s], l);

    __shared__ float sv[256 * KK];
    __shared__ int   si[256 * KK];
#pragma unroll
    for (int k = 0; k < KK; k++) { sv[tid * KK + k] = v[k]; si[tid * KK + k] = id[k]; }

    for (int step = 128; step >= 1; step >>= 1) {
        __syncthreads();
        if (tid < step) {
            float* av = &sv[tid * KK]; int* ai = &si[tid * KK];
            float mv[KK]; int mi[KK];
#pragma unroll
            for (int k = 0; k < KK; k++) { mv[k] = av[k]; mi[k] = ai[k]; }
#pragma unroll
            for (int k = 0; k < KK; k++)
                tk_insert(mv, mi, sv[(tid + step) * KK + k], si[(tid + step) * KK + k]);
#pragma unroll
            for (int k = 0; k < KK; k++) { av[k] = mv[k]; ai[k] = mi[k]; }
        }
    }
    __syncthreads();
    if (tid == 0) {
        float m = sv[0];
        float e[KK]; float sum = 0.f;
#pragma unroll
        for (int k = 0; k < KK; k++) { e[k] = expf(sv[k] - m); sum += e[k]; }
        float inv = 1.f / sum;
#pragma unroll
        for (int k = 0; k < KK; k++) { wgto[bs * KK + k] = e[k] * inv; idxo[bs * KK + k] = si[k]; }
    }
}

// ---------------- weighted gather -> fp16 hi/lo ----------------
__global__ void gatherw_kernel(const float* __restrict__ x, const int* __restrict__ idx,
                               const float* __restrict__ wgt,
                               __half* __restrict__ xwh, __half* __restrict__ xwl) {
    int bs = blockIdx.x;
    int b = bs / SS;
    const float* r0 = x + ((long)b * LL + idx[bs * KK + 0]) * DD;
    const float* r1 = x + ((long)b * LL + idx[bs * KK + 1]) * DD;
    const float* r2 = x + ((long)b * LL + idx[bs * KK + 2]) * DD;
    const float* r3 = x + ((long)b * LL + idx[bs * KK + 3]) * DD;
    float w0 = wgt[bs * KK + 0], w1 = wgt[bs * KK + 1];
    float w2 = wgt[bs * KK + 2], w3 = wgt[bs * KK + 3];
    for (int d = threadIdx.x; d < DD; d += blockDim.x) {
        float v = w0 * r0[d] + w1 * r1[d] + w2 * r2[d] + w3 * r3[d];
        __half h, lo;
        split1(v, h, lo);
        xwh[(long)bs * DD + d] = h;
        xwl[(long)bs * DD + d] = lo;
    }
}

// ---------------- ws update + rms ----------------
__global__ void ws_update_kernel(const float* __restrict__ P, const float* __restrict__ wgt,
                                 const float* __restrict__ wb, const float* __restrict__ npw,
                                 float* __restrict__ ws,
                                 __half* __restrict__ wsh, __half* __restrict__ wsl) {
    int bs = blockIdx.x;
    __shared__ float t[DD];
    __shared__ float red[256];
    float sumw = wgt[bs * KK + 0] + wgt[bs * KK + 1] + wgt[bs * KK + 2] + wgt[bs * KK + 3];
    const long MN = (long)BB * SS * DD;
    long rr = (long)bs * DD;
    float ssp = 0.f;
    for (int d = threadIdx.x; d < DD; d += 256) {
        float a = sumw * wb[d];
#pragma unroll
        for (int sp = 0; sp < 8; sp++) a += P[(long)sp * MN + rr + d];
        float v = ws[rr + d] + a;
        t[d] = v; ssp += v * v;
    }
    red[threadIdx.x] = ssp; __syncthreads();
    for (int st = 128; st; st >>= 1) {
        if (threadIdx.x < st) red[threadIdx.x] += red[threadIdx.x + st];
        __syncthreads();
    }
    float rinv = rsqrtf(red[0] * (1.f / DD) + EPSF);
    for (int d = threadIdx.x; d < DD; d += 256) {
        float v = t[d] * rinv * npw[d];
        ws[rr + d] = v;
        __half h, lo;
        split1(v, h, lo);
        wsh[rr + d] = h;
        wsl[rr + d] = lo;
    }
}

// ---------------- fold kk with wq: G[b,(h,s),d] ----------------
__global__ __launch_bounds__(128) void gfold_kernel(const float* __restrict__ kv,
                                                    const float* __restrict__ wq,
                                                    __half* __restrict__ Gh,
                                                    __half* __restrict__ Gl) {
    int b = blockIdx.y / HH, h = blockIdx.y % HH;
    int d0 = blockIdx.x * 128;
    __shared__ float ks[SS][HD];
    __shared__ float wqs[HD][128 + 1];
    for (int e = threadIdx.x; e < SS * HD; e += 128) {
        int s = e >> 6, i = e & 63;
        ks[s][i] = kv[((long)b * SS + s) * (2 * DD) + h * HD + i];
    }
    for (int e = threadIdx.x; e < HD * 128; e += 128) {
        int i = e >> 7, c = e & 127;
        wqs[i][c] = wq[(long)(h * HD + i) * DD + d0 + c];
    }
    __syncthreads();
    int d = threadIdx.x;
    float acc[SS];
#pragma unroll
    for (int s = 0; s < SS; s++) acc[s] = 0.f;
#pragma unroll
    for (int i = 0; i < HD; i++) {
        float w = wqs[i][d];
#pragma unroll
        for (int s = 0; s < SS; s++) acc[s] += w * ks[s][i];
    }
#pragma unroll
    for (int s = 0; s < SS; s++) {
        long off = ((long)b * HH * SS + h * SS + s) * DD + d0 + d;
        __half hh, ll;
        split1(acc[s], hh, ll);
        Gh[off] = hh;
        Gl[off] = ll;
    }
}

// ---------------- sbias[b,h,s] ----------------
__global__ void sbias_kernel(const float* __restrict__ kv, const float* __restrict__ bq,
                             float* __restrict__ sbias) {
    int bh = blockIdx.x;
    int b = bh / HH, h = bh % HH;
    int lane = threadIdx.x;
    for (int s = 0; s < SS; s++) {
        float a = 0.f;
        for (int i = lane; i < HD; i += 32)
            a += bq[h * HD + i] * kv[((long)b * SS + s) * (2 * DD) + h * HD + i];
#pragma unroll
        for (int o = 16; o; o >>= 1) a += __shfl_xor_sync(0xffffffffu, a, o);
        if (lane == 0) sbias[(long)bh * SS + s] = a;
    }
}

// ---------------- fold vv with out_proj -> voT ----------------
__global__ __launch_bounds__(128) void vo_kernel(const float* __restrict__ kv,
                                                 const float* __restrict__ wout,
                                                 __half* __restrict__ voTh,
                                                 __half* __restrict__ voTl) {
    int b = blockIdx.y / HH, h = blockIdx.y % HH;
    int d0 = blockIdx.x * 128;
    __shared__ float vs[SS][HD];
    __shared__ float wsm[128][HD + 1];
    for (int e = threadIdx.x; e < SS * HD; e += 128) {
        int s = e >> 6, i = e & 63;
        vs[s][i] = kv[((long)b * SS + s) * (2 * DD) + DD + h * HD + i];
    }
    for (int e = threadIdx.x; e < 128 * HD; e += 128) {
        int r = e >> 6, i = e & 63;
        wsm[r][i] = wout[(long)(d0 + r) * DD + h * HD + i];
    }
    __syncthreads();
    int d = threadIdx.x;
    float acc[SS];
#pragma unroll
    for (int s = 0; s < SS; s++) acc[s] = 0.f;
#pragma unroll
    for (int i = 0; i < HD; i++) {
        float w = wsm[d][i];
#pragma unroll
        for (int s = 0; s < SS; s++) acc[s] += w * vs[s][i];
    }
    long base = ((long)b * DD + d0 + d) * (HH * SS) + h * SS;
#pragma unroll
    for (int s = 0; s < SS; s++) {
        __half hh, ll;
        split1(acc[s], hh, ll);
        voTh[base + s] = hh;
        voTl[base + s] = ll;
    }
}

// ---------------- x = rms(x + xb) -> fp32 out (+ hi/lo), float4 ----------------
__global__ void resid_rms_kernel(const float* __restrict__ xin, const float* __restrict__ xb,
                                 const float* __restrict__ npw, float* __restrict__ xout,
                                 __half* __restrict__ xh, __half* __restrict__ xl) {
    long row = blockIdx.x;
    __shared__ float t[DD];
    __shared__ float red[256];
    const float4* a4 = (const float4*)(xin + row * DD);
    const float4* c4 = (const float4*)(xb + row * DD);
    float4* t4 = (float4*)t;
    float ssp = 0.f;
#pragma unroll
    for (int q = 0; q < 2; q++) {
        int i4 = threadIdx.x + q * 256;
        float4 a = a4[i4], c = c4[i4];
        float4 v; v.x = a.x + c.x; v.y = a.y + c.y; v.z = a.z + c.z; v.w = a.w + c.w;
        t4[i4] = v;
        ssp += v.x * v.x + v.y * v.y + v.z * v.z + v.w * v.w;
    }
    red[threadIdx.x] = ssp; __syncthreads();
    for (int st = 128; st; st >>= 1) {
        if (threadIdx.x < st) red[threadIdx.x] += red[threadIdx.x + st];
        __syncthreads();
    }
    float rinv = rsqrtf(red[0] * (1.f / DD) + EPSF);
    const float4* w4 = (const float4*)npw;
    float4* o4 = (float4*)(xout + row * DD);
    __half2* h2 = (__half2*)(xh + row * DD);
    __half2* l2 = (__half2*)(xl + row * DD);
#pragma unroll
    for (int q = 0; q < 2; q++) {
        int i4 = threadIdx.x + q * 256;
        float4 v = t4[i4], w = w4[i4];
        v.x *= rinv * w.x; v.y *= rinv * w.y; v.z *= rinv * w.z; v.w *= rinv * w.w;
        o4[i4] = v;
        __half h[4], l[4];
        split1(v.x, h[0], l[0]); split1(v.y, h[1], l[1]);
        split1(v.z, h[2], l[2]); split1(v.w, h[3], l[3]);
        h2[i4 * 2]     = __halves2half2(h[0], h[1]);
        h2[i4 * 2 + 1] = __halves2half2(h[2], h[3]);
        l2[i4 * 2]     = __halves2half2(l[0], l[1]);
        l2[i4 * 2 + 1] = __halves2half2(l[2], l[3]);
    }
}

// ---------------- host launch ----------------
static inline void run_split(const float* src, __half* hi, __half* lo, long n) {
    long n4 = n >> 2;
    split4_kernel<<<(int)((n4 + 255) / 256), 256>>>(src, hi, lo, n4);
}

#define CW_SMEM (SS * DD * 4)

extern "C" void kernel_launch(void* const* d_in, const int* in_sizes, int n_in,
                              void* d_out, int out_size) {
    const float* x_in       = (const float*)d_in[0];
    const float* workspace  = (const float*)d_in[1];
    const float* compete_w  = (const float*)d_in[2];
    const float* compete_b  = (const float*)d_in[3];
    const float* write_w    = (const float*)d_in[4];
    const float* write_b    = (const float*)d_in[5];
    const float* in_proj_w  = (const float*)d_in[6];
    const float* in_proj_b  = (const float*)d_in[7];
    const float* out_proj_w = (const float*)d_in[8];
    const float* out_proj_b = (const float*)d_in[9];
    const float* norm_pre_w  = (const float*)d_in[12];
    const float* norm_post_w = (const float*)d_in[13];

    cudaFuncSetAttribute(compete_kernel, cudaFuncAttributeMaxDynamicSharedMemorySize, CW_SMEM);

    void *p;
    float *px, *pxb, *plog, *pws, *pkv, *ppart, *pwgt, *psb;
    int *pidx;
    __half *pxh, *pxl, *pwkvh, *pwkvl, *pwwh, *pwwl, *pGh, *pGl;
    __half *patth, *pvoTh, *pvoTl, *pwsh, *pwsl, *pxwh, *pxwl;
    cudaGetSymbolAddress(&p, g_x);     px   = (float*)p;
    cudaGetSymbolAddress(&p, g_xb);    pxb  = (float*)p;
    cudaGetSymbolAddress(&p, g_logits); plog = (float*)p;
    cudaGetSymbolAddress(&p, g_ws);    pws  = (float*)p;
    cudaGetSymbolAddress(&p, g_kv);    pkv  = (float*)p;
    cudaGetSymbolAddress(&p, g_part);  ppart = (float*)p;
    cudaGetSymbolAddress(&p, g_wgt);   pwgt = (float*)p;
    cudaGetSymbolAddress(&p, g_sbias); psb  = (float*)p;
    cudaGetSymbolAddress(&p, g_idx);   pidx = (int*)p;
    cudaGetSymbolAddress(&p, g_xh);    pxh  = (__half*)p;
    cudaGetSymbolAddress(&p, g_xl);    pxl  = (__half*)p;
    cudaGetSymbolAddress(&p, g_wkvh);  pwkvh = (__half*)p;
    cudaGetSymbolAddress(&p, g_wkvl);  pwkvl = (__half*)p;
    cudaGetSymbolAddress(&p, g_wwh);   pwwh = (__half*)p;
    cudaGetSymbolAddress(&p, g_wwl);   pwwl = (__half*)p;
    cudaGetSymbolAddress(&p, g_Gh);    pGh  = (__half*)p;
    cudaGetSymbolAddress(&p, g_Gl);    pGl  = (__half*)p;
    cudaGetSymbolAddress(&p, g_atth);  patth = (__half*)p;
    cudaGetSymbolAddress(&p, g_voTh);  pvoTh = (__half*)p;
    cudaGetSymbolAddress(&p, g_voTl);  pvoTl = (__half*)p;
    cudaGetSymbolAddress(&p, g_wsh);   pwsh = (__half*)p;
    cudaGetSymbolAddress(&p, g_wsl);   pwsl = (__half*)p;
    cudaGetSymbolAddress(&p, g_xwh);   pxwh = (__half*)p;
    cudaGetSymbolAddress(&p, g_xwl);   pxwl = (__half*)p;

    // init: x <- input (fp32 + hi/lo), ws <- broadcast(workspace)
    {
        long n4 = (long)BB * LL * DD / 4;
        copysplit_kernel<<<(int)((n4 + 255) / 256), 256>>>(x_in, px, pxh, pxl, n4);
        init_ws_kernel<<<BB * SS, 256>>>(workspace, pws);
    }
    // weight splits (once per launch); wq stays fp32 (used only in gfold)
    run_split(in_proj_w + (long)DD * DD, pwkvh, pwkvl, (long)2 * DD * DD);
    run_split(write_w, pwwh, pwwl, (long)DD * DD);

    for (int it = 0; it < NB; it++) {
        // 1. compete logits (cw in smem)
        compete_kernel<<<BB * LL / 32, 512, CW_SMEM>>>(px, compete_w, compete_b, norm_pre_w, plog);
        // 2. top-k + softmax weights (tree merge)
        topk_kernel<<<BB * SS, 256>>>(plog, pidx, pwgt);
        // 3. weighted gather: xw = sum_k wgt_k x_k (64 rows)
        gatherw_kernel<<<BB * SS, 256>>>(px, pidx, pwgt, pxwh, pxwl);
        // 4. write projection (64 x 2048 x 2048), split-K=8 -> partials
        {
            dim3 grid(DD / 128, 1, 8);
            gemm3p_kernel<<<grid, 256>>>(pxwh, pxwl, pwwh, pwwl, ppart,
                                         BB * SS, DD, DD, DD / 8);
        }
        // 5. workspace update + rms (+hi/lo), reduces partials inline
        ws_update_kernel<<<BB * SS, 256>>>(ppart, pwgt, write_b, norm_post_w, pws, pwsh, pwsl);
        // 6. kk|vv projection (64 x 4096 x 2048), split-K=8 -> partials -> reduce
        {
            dim3 grid((2 * DD) / 128, 1, 8);
            gemm3p_kernel<<<grid, 256>>>(pwsh, pwsl, pwkvh, pwkvl, ppart,
                                         BB * SS, 2 * DD, DD, DD / 8);
            kvred_kernel<<<256, 256>>>(ppart, in_proj_b + DD, pkv);
        }
        // 7. fold kk with wq -> G ; sbias
        {
            dim3 grid(DD / 128, BB * HH, 1);
            gfold_kernel<<<grid, 128>>>(pkv, in_proj_w, pGh, pGl);
            sbias_kernel<<<BB * HH, 32>>>(pkv, in_proj_b, psb);
        }
        // 8. fold vv with out_proj -> voT
        {
            dim3 grid(DD / 128, BB * HH, 1);
            vo_kernel<<<grid, 128>>>(pkv, out_proj_w, pvoTh, pvoTl);
        }
        // 9. scores GEMM (3-term chained) + fused softmax -> att fp16 hi only
        {
            dim3 grid(HH * SS / 128, LL / 128, BB);
            gemm3s_kernel<<<grid, 256>>>(pxh, pxl, pGh, pGl, psb, patth,
                                         DD, (long)LL * DD, (long)HH * SS * DD);
        }
        // 10. x_b = att @ voT^T + out_proj_b — 2-term GEMM (hh + h*lo)
        {
            dim3 grid(DD / 128, LL / 128, BB);
            gemm2_kernel<<<grid, 256>>>(patth, pvoTh, pvoTl, out_proj_b, pxb,
                                        LL, DD, HH * SS,
                                        (long)LL * HH * SS, (long)DD * HH * SS,
                                        (long)LL * DD);
        }
        // 11. x = rms(x + x_b) (+hi/lo); last round writes d_out
        float* xdst = (it == NB - 1) ? (float*)d_out : px;
        resid_rms_kernel<<<BB * LL, 256>>>(px, pxb, norm_post_w, xdst, pxh, pxl);
    }
}

// round 15
// speedup vs baseline: 1.1002x; 1.1002x over previous
#include <cuda_runtime.h>
#include <cuda_bf16.h>
#include <cuda_fp16.h>
#include <cstdint>

// ---------------- problem constants ----------------
#define BB 4
#define LL 2048
#define DD 2048
#define SS 16
#define KK 4
#define NB 2
#define HH 32
#define HD 64
#define EPSF 1e-6f

// ---------------- device scratch (no allocs allowed) ----------------
__device__ float g_x[BB * LL * DD];
__device__ float g_xb[BB * LL * DD];
__device__ float g_logits[BB * LL * SS];
__device__ float g_ws[BB * SS * DD];
__device__ float g_kv[BB * SS * 2 * DD];
__device__ float g_part[8 * 64 * 4096];       // split-K partials
__device__ float g_wgt[BB * SS * KK];
__device__ float g_sbias[BB * HH * SS];
__device__ int   g_idx[BB * SS * KK];

// bf16 hi/lo split operand buffers (x, weights, G)
__device__ __nv_bfloat16 g_xh[BB * LL * DD],  g_xl[BB * LL * DD];
__device__ __nv_bfloat16 g_wkvh[2 * DD * DD],  g_wkvl[2 * DD * DD];
__device__ __nv_bfloat16 g_wwh[DD * DD],       g_wwl[DD * DD];
__device__ __nv_bfloat16 g_Gh[BB * HH * SS * DD], g_Gl[BB * HH * SS * DD];
__device__ __nv_bfloat16 g_wsh[BB * SS * DD],  g_wsl[BB * SS * DD];
__device__ __nv_bfloat16 g_xwh[BB * SS * DD],  g_xwl[BB * SS * DD];
// fp16 buffers for the att -> xb path (11-bit mantissa makes 2-term xb safe)
__device__ __half g_atth[BB * LL * HH * SS];
__device__ __half g_voTh[BB * DD * HH * SS], g_voTl[BB * DD * HH * SS];

// ---------------- PTX helpers ----------------
__device__ __forceinline__ void cp16(void* sdst, const void* gsrc) {
    uint32_t d = (uint32_t)__cvta_generic_to_shared(sdst);
    asm volatile("cp.async.cg.shared.global [%0], [%1], 16;\n" :: "r"(d), "l"(gsrc));
}
__device__ __forceinline__ void cp_commit() { asm volatile("cp.async.commit_group;\n"); }
template <int N> __device__ __forceinline__ void cp_wait() {
    asm volatile("cp.async.wait_group %0;\n" :: "n"(N));
}
__device__ __forceinline__ void ldsm4(uint32_t* r, uint32_t saddr) {
    asm volatile("ldmatrix.sync.aligned.m8n8.x4.shared.b16 {%0,%1,%2,%3}, [%4];\n"
                 : "=r"(r[0]), "=r"(r[1]), "=r"(r[2]), "=r"(r[3]) : "r"(saddr));
}
// bf16 inputs, f32 accumulator
__device__ __forceinline__ void mma_bf(float* c, const uint32_t* a, uint32_t b0, uint32_t b1) {
    asm volatile("mma.sync.aligned.m16n8k16.row.col.f32.bf16.bf16.f32 "
                 "{%0,%1,%2,%3}, {%4,%5,%6,%7}, {%8,%9}, {%0,%1,%2,%3};\n"
                 : "+f"(c[0]), "+f"(c[1]), "+f"(c[2]), "+f"(c[3])
                 : "r"(a[0]), "r"(a[1]), "r"(a[2]), "r"(a[3]), "r"(b0), "r"(b1));
}
// fp16 inputs, f32 accumulator
__device__ __forceinline__ void mma_fp(float* c, const uint32_t* a, uint32_t b0, uint32_t b1) {
    asm volatile("mma.sync.aligned.m16n8k16.row.col.f32.f16.f16.f32 "
                 "{%0,%1,%2,%3}, {%4,%5,%6,%7}, {%8,%9}, {%0,%1,%2,%3};\n"
                 : "+f"(c[0]), "+f"(c[1]), "+f"(c[2]), "+f"(c[3])
                 : "r"(a[0]), "r"(a[1]), "r"(a[2]), "r"(a[3]), "r"(b0), "r"(b1));
}
__device__ __forceinline__ void split1(float v, __nv_bfloat16& h, __nv_bfloat16& l) {
    h = __float2bfloat16(v);
    l = __float2bfloat16(v - __bfloat162float(h));
}
__device__ __forceinline__ void split1h(float v, __half& h, __half& l) {
    h = __float2half_rn(v);
    l = __float2half_rn(v - __half2float(h));
}
__device__ __forceinline__ uint32_t smem_u32(const void* p) {
    return (uint32_t)__cvta_generic_to_shared(p);
}

// ---------------- splits ----------------
__global__ void split4_kernel(const float* __restrict__ src, __nv_bfloat16* __restrict__ hi,
                              __nv_bfloat16* __restrict__ lo, long n4) {
    long i = (long)blockIdx.x * blockDim.x + threadIdx.x;
    if (i >= n4) return;
    float4 v = ((const float4*)src)[i];
    __nv_bfloat16 h[4], l[4];
    split1(v.x, h[0], l[0]); split1(v.y, h[1], l[1]);
    split1(v.z, h[2], l[2]); split1(v.w, h[3], l[3]);
    __nv_bfloat162 ph0; ph0.x = h[0]; ph0.y = h[1];
    __nv_bfloat162 ph1; ph1.x = h[2]; ph1.y = h[3];
    __nv_bfloat162 pl0; pl0.x = l[0]; pl0.y = l[1];
    __nv_bfloat162 pl1; pl1.x = l[2]; pl1.y = l[3];
    ((__nv_bfloat162*)hi)[2 * i]     = ph0;
    ((__nv_bfloat162*)hi)[2 * i + 1] = ph1;
    ((__nv_bfloat162*)lo)[2 * i]     = pl0;
    ((__nv_bfloat162*)lo)[2 * i + 1] = pl1;
}

__global__ void copysplit_kernel(const float* __restrict__ src, float* __restrict__ dst,
                                 __nv_bfloat16* __restrict__ hi, __nv_bfloat16* __restrict__ lo,
                                 long n4) {
    long i = (long)blockIdx.x * blockDim.x + threadIdx.x;
    if (i >= n4) return;
    float4 v = ((const float4*)src)[i];
    ((float4*)dst)[i] = v;
    __nv_bfloat16 h[4], l[4];
    split1(v.x, h[0], l[0]); split1(v.y, h[1], l[1]);
    split1(v.z, h[2], l[2]); split1(v.w, h[3], l[3]);
    __nv_bfloat162 ph0; ph0.x = h[0]; ph0.y = h[1];
    __nv_bfloat162 ph1; ph1.x = h[2]; ph1.y = h[3];
    __nv_bfloat162 pl0; pl0.x = l[0]; pl0.y = l[1];
    __nv_bfloat162 pl1; pl1.x = l[2]; pl1.y = l[3];
    ((__nv_bfloat162*)hi)[2 * i]     = ph0;
    ((__nv_bfloat162*)hi)[2 * i + 1] = ph1;
    ((__nv_bfloat162*)lo)[2 * i]     = pl0;
    ((__nv_bfloat162*)lo)[2 * i + 1] = pl1;
}

__global__ void init_ws_kernel(const float* __restrict__ wsrc, float* __restrict__ ws) {
    int bs = blockIdx.x;
    int s = bs % SS;
    for (int d = threadIdx.x; d < DD; d += blockDim.x)
        ws[(long)bs * DD + d] = wsrc[(long)s * DD + d];
}

// ---------------- 2-term fp16 GEMM for xb: C = A @ (Bh+Bl)^T + bias ----------------
// A single fp16 (att, hi only); both sweeps f32 acc. No extra accumulator state.
__global__ __launch_bounds__(256) void gemm2_kernel(
    const __half* __restrict__ A,
    const __half* __restrict__ Bh, const __half* __restrict__ Bl,
    const float* __restrict__ bias, float* __restrict__ C,
    int M, int N, int K, long bsA, long bsB, long bsC) {
    A  += (long)blockIdx.z * bsA;
    Bh += (long)blockIdx.z * bsB; Bl += (long)blockIdx.z * bsB;
    C  += (long)blockIdx.z * bsC;

    __shared__ __align__(16) __half sm[2][3][128 * 24];

    const int tid = threadIdx.x;
    const int m0 = blockIdx.y * 128, n0 = blockIdx.x * 128;

    const int lrow = tid >> 1, lhalf = tid & 1;
    const long aoff = (long)(m0 + lrow) * K + lhalf * 8;
    const long boff = (long)(n0 + lrow) * K + lhalf * 8;
    const uint32_t soff = lrow * 24 + lhalf * 8;

    const int NT = K >> 4;

    cp16(&sm[0][0][soff], A + aoff);
    cp16(&sm[0][1][soff], Bh + boff);
    cp16(&sm[0][2][soff], Bl + boff);
    cp_commit();

    const int lane = tid & 31, warp = tid >> 5;
    const int wm = (warp & 3) * 32;
    const int wn = (warp >> 2) * 64;

    uint32_t a_row = wm + (lane & 7) + ((lane >> 3) & 1) * 8;
    uint32_t a_k   = (lane >> 4) * 8;
    uint32_t aoffs[2];
    aoffs[0] = ((a_row) * 24 + a_k) * 2;
    aoffs[1] = ((a_row + 16) * 24 + a_k) * 2;
    uint32_t b_row = wn + (lane & 7) + ((lane >> 4) ? 8 : 0);
    uint32_t b_k   = ((lane >> 3) & 1) * 8;
    uint32_t boffs[4];
#pragma unroll
    for (int p = 0; p < 4; p++) boffs[p] = ((b_row + p * 16) * 24 + b_k) * 2;

    const uint32_t smbase = smem_u32(&sm[0][0][0]);
    const uint32_t ARR = 128 * 24 * 2;

    float acc[2][8][4];
#pragma unroll
    for (int mt = 0; mt < 2; mt++)
#pragma unroll
        for (int nt = 0; nt < 8; nt++)
#pragma unroll
            for (int j = 0; j < 4; j++) acc[mt][nt][j] = 0.f;

    for (int kt = 0; kt < NT; kt++) {
        const int cur = kt & 1;
        if (kt + 1 < NT) {
            const int nx = cur ^ 1;
            const long kb = (long)(kt + 1) << 4;
            cp16(&sm[nx][0][soff], A + aoff + kb);
            cp16(&sm[nx][1][soff], Bh + boff + kb);
            cp16(&sm[nx][2][soff], Bl + boff + kb);
            cp_commit();
            cp_wait<1>();
        } else {
            cp_wait<0>();
        }
        __syncthreads();

        const uint32_t bA  = smbase + (cur * 3 + 0) * ARR;
        const uint32_t bBh = smbase + (cur * 3 + 1) * ARR;
        const uint32_t bBl = smbase + (cur * 3 + 2) * ARR;

        uint32_t ah[2][4], bh[4][4], bl[4][4];
#pragma unroll
        for (int mt = 0; mt < 2; mt++) ldsm4(ah[mt], bA + aoffs[mt]);
#pragma unroll
        for (int p = 0; p < 4; p++) {
            ldsm4(bh[p], bBh + boffs[p]);
            ldsm4(bl[p], bBl + boffs[p]);
        }

#pragma unroll
        for (int mt = 0; mt < 2; mt++)
#pragma unroll
            for (int nt = 0; nt < 8; nt++)
                mma_fp(acc[mt][nt], ah[mt],
                       bh[nt >> 1][(nt & 1) * 2], bh[nt >> 1][(nt & 1) * 2 + 1]);
#pragma unroll
        for (int mt = 0; mt < 2; mt++)
#pragma unroll
            for (int nt = 0; nt < 8; nt++)
                mma_fp(acc[mt][nt], ah[mt],
                       bl[nt >> 1][(nt & 1) * 2], bl[nt >> 1][(nt & 1) * 2 + 1]);
        __syncthreads();
    }

#pragma unroll
    for (int mt = 0; mt < 2; mt++) {
        int r0 = m0 + wm + mt * 16 + (lane >> 2);
#pragma unroll
        for (int nt = 0; nt < 8; nt++) {
            int cc = n0 + wn + nt * 8 + (lane & 3) * 2;
            float b0v = bias[cc], b1v = bias[cc + 1];
            float* c = acc[mt][nt];
            float2 o0; o0.x = c[0] + b0v; o0.y = c[1] + b1v;
            *(float2*)(C + (long)r0 * N + cc) = o0;
            float2 o1; o1.x = c[2] + b0v; o1.y = c[3] + b1v;
            *(float2*)(C + (long)(r0 + 8) * N + cc) = o1;
        }
    }
}

// ---------------- scores GEMM (bf16x3, per-tile sweeps) + fused softmax -> fp16 att ----------------
__global__ __launch_bounds__(256) void gemm3s_kernel(
    const __nv_bfloat16* __restrict__ Ah, const __nv_bfloat16* __restrict__ Al,
    const __nv_bfloat16* __restrict__ Bh, const __nv_bfloat16* __restrict__ Bl,
    const float* __restrict__ sbias,
    __half* __restrict__ atth,
    int K, long bsA, long bsB) {
    const int b = blockIdx.z;
    Ah += (long)b * bsA; Al += (long)b * bsA;
    Bh += (long)b * bsB; Bl += (long)b * bsB;
    const float* sb = sbias + (long)b * (HH * SS);

    __shared__ __align__(16) __nv_bfloat16 sm[2][4][128 * 24];

    const int tid = threadIdx.x;
    const int m0 = blockIdx.y * 128, n0 = blockIdx.x * 128;

    const int lrow = tid >> 1, lhalf = tid & 1;
    const long aoff = (long)(m0 + lrow) * K + lhalf * 8;
    const long boff = (long)(n0 + lrow) * K + lhalf * 8;
    const uint32_t soff = lrow * 24 + lhalf * 8;

    const int NT = K >> 4;

    cp16(&sm[0][0][soff], Ah + aoff);
    cp16(&sm[0][1][soff], Al + aoff);
    cp16(&sm[0][2][soff], Bh + boff);
    cp16(&sm[0][3][soff], Bl + boff);
    cp_commit();

    const int lane = tid & 31, warp = tid >> 5;
    const int wm = (warp & 3) * 32;
    const int wn = (warp >> 2) * 64;

    uint32_t a_row = wm + (lane & 7) + ((lane >> 3) & 1) * 8;
    uint32_t a_k   = (lane >> 4) * 8;
    uint32_t aoffs[2];
    aoffs[0] = ((a_row) * 24 + a_k) * 2;
    aoffs[1] = ((a_row + 16) * 24 + a_k) * 2;
    uint32_t b_row = wn + (lane & 7) + ((lane >> 4) ? 8 : 0);
    uint32_t b_k   = ((lane >> 3) & 1) * 8;
    uint32_t boffs[4];
#pragma unroll
    for (int p = 0; p < 4; p++) boffs[p] = ((b_row + p * 16) * 24 + b_k) * 2;

    const uint32_t smbase = smem_u32(&sm[0][0][0]);
    const uint32_t ARR = 128 * 24 * 2;

    float acc[2][8][4];
#pragma unroll
    for (int mt = 0; mt < 2; mt++)
#pragma unroll
        for (int nt = 0; nt < 8; nt++)
#pragma unroll
            for (int j = 0; j < 4; j++) acc[mt][nt][j] = 0.f;

    for (int kt = 0; kt < NT; kt++) {
        const int cur = kt & 1;
        if (kt + 1 < NT) {
            const int nx = cur ^ 1;
            const long kb = (long)(kt + 1) << 4;
            cp16(&sm[nx][0][soff], Ah + aoff + kb);
            cp16(&sm[nx][1][soff], Al + aoff + kb);
            cp16(&sm[nx][2][soff], Bh + boff + kb);
            cp16(&sm[nx][3][soff], Bl + boff + kb);
            cp_commit();
            cp_wait<1>();
        } else {
            cp_wait<0>();
        }
        __syncthreads();

        const uint32_t bAh = smbase + (cur * 4 + 0) * ARR;
        const uint32_t bAl = smbase + (cur * 4 + 1) * ARR;
        const uint32_t bBh = smbase + (cur * 4 + 2) * ARR;
        const uint32_t bBl = smbase + (cur * 4 + 3) * ARR;

        uint32_t ah[2][4], al[2][4], bh[4][4], bl[4][4];
#pragma unroll
        for (int mt = 0; mt < 2; mt++) {
            ldsm4(ah[mt], bAh + aoffs[mt]);
            ldsm4(al[mt], bAl + aoffs[mt]);
        }
#pragma unroll
        for (int p = 0; p < 4; p++) {
            ldsm4(bh[p], bBh + boffs[p]);
            ldsm4(bl[p], bBl + boffs[p]);
        }

#pragma unroll
        for (int mt = 0; mt < 2; mt++)
#pragma unroll
            for (int nt = 0; nt < 8; nt++)
                mma_bf(acc[mt][nt], ah[mt],
                       bh[nt >> 1][(nt & 1) * 2], bh[nt >> 1][(nt & 1) * 2 + 1]);
#pragma unroll
        for (int mt = 0; mt < 2; mt++)
#pragma unroll
            for (int nt = 0; nt < 8; nt++)
                mma_bf(acc[mt][nt], ah[mt],
                       bl[nt >> 1][(nt & 1) * 2], bl[nt >> 1][(nt & 1) * 2 + 1]);
#pragma unroll
        for (int mt = 0; mt < 2; mt++)
#pragma unroll
            for (int nt = 0; nt < 8; nt++)
                mma_bf(acc[mt][nt], al[mt],
                       bh[nt >> 1][(nt & 1) * 2], bh[nt >> 1][(nt & 1) * 2 + 1]);
        __syncthreads();
    }

    // fused softmax epilogue over 16-col head groups (quad shfl) -> fp16 att
#pragma unroll
    for (int mt = 0; mt < 2; mt++) {
        int r0 = m0 + wm + mt * 16 + (lane >> 2);
#pragma unroll
        for (int half = 0; half < 2; half++) {
            int row = r0 + half * 8;
            long obase = ((long)b * LL + row) * (HH * SS) + n0;
#pragma unroll
            for (int g = 0; g < 4; g++) {
                int c0 = wn + (2 * g) * 8 + (lane & 3) * 2;
                int c1 = wn + (2 * g + 1) * 8 + (lane & 3) * 2;
                float x0 = (acc[mt][2 * g][half * 2 + 0]     + sb[n0 + c0])     * 0.125f;
                float x1 = (acc[mt][2 * g][half * 2 + 1]     + sb[n0 + c0 + 1]) * 0.125f;
                float x2 = (acc[mt][2 * g + 1][half * 2 + 0] + sb[n0 + c1])     * 0.125f;
                float x3 = (acc[mt][2 * g + 1][half * 2 + 1] + sb[n0 + c1 + 1]) * 0.125f;
                float mx = fmaxf(fmaxf(x0, x1), fmaxf(x2, x3));
                mx = fmaxf(mx, __shfl_xor_sync(0xffffffffu, mx, 1));
                mx = fmaxf(mx, __shfl_xor_sync(0xffffffffu, mx, 2));
                float e0 = expf(x0 - mx), e1 = expf(x1 - mx);
                float e2 = expf(x2 - mx), e3 = expf(x3 - mx);
                float s = e0 + e1 + e2 + e3;
                s += __shfl_xor_sync(0xffffffffu, s, 1);
                s += __shfl_xor_sync(0xffffffffu, s, 2);
                float inv = 1.f / s;
                *(__half2*)(atth + obase + c0) =
                    __halves2half2(__float2half_rn(e0 * inv), __float2half_rn(e1 * inv));
                *(__half2*)(atth + obase + c1) =
                    __halves2half2(__float2half_rn(e2 * inv), __float2half_rn(e3 * inv));
            }
        }
    }
}

// ---------------- split-K bf16x3 GEMM: partial C (no bias) ----------------
__global__ __launch_bounds__(256) void gemm3p_kernel(
    const __nv_bfloat16* __restrict__ Ah, const __nv_bfloat16* __restrict__ Al,
    const __nv_bfloat16* __restrict__ Bh, const __nv_bfloat16* __restrict__ Bl,
    float* __restrict__ P, int M, int N, int K, int kLen) {
    const int ksplit = blockIdx.z;
    const int k0base = ksplit * kLen;
    P += (long)ksplit * M * N;

    __shared__ __align__(16) __nv_bfloat16 sm[2][4][128 * 24];

    const int tid = threadIdx.x;
    const int m0 = blockIdx.y * 128, n0 = blockIdx.x * 128;

    const int lrow = tid >> 1, lhalf = tid & 1;
    int arow = m0 + lrow; if (arow >= M) arow = M - 1;
    int brow = n0 + lrow; if (brow >= N) brow = N - 1;
    const long aoff = (long)arow * K + k0base + lhalf * 8;
    const long boff = (long)brow * K + k0base + lhalf * 8;
    const uint32_t soff = lrow * 24 + lhalf * 8;

    const int NT = kLen >> 4;

    cp16(&sm[0][0][soff], Ah + aoff);
    cp16(&sm[0][1][soff], Al + aoff);
    cp16(&sm[0][2][soff], Bh + boff);
    cp16(&sm[0][3][soff], Bl + boff);
    cp_commit();

    const int lane = tid & 31, warp = tid >> 5;
    const int wm = (warp & 3) * 32;
    const int wn = (warp >> 2) * 64;

    uint32_t a_row = wm + (lane & 7) + ((lane >> 3) & 1) * 8;
    uint32_t a_k   = (lane >> 4) * 8;
    uint32_t aoffs[2];
    aoffs[0] = ((a_row) * 24 + a_k) * 2;
    aoffs[1] = ((a_row + 16) * 24 + a_k) * 2;
    uint32_t b_row = wn + (lane & 7) + ((lane >> 4) ? 8 : 0);
    uint32_t b_k   = ((lane >> 3) & 1) * 8;
    uint32_t boffs[4];
#pragma unroll
    for (int p = 0; p < 4; p++) boffs[p] = ((b_row + p * 16) * 24 + b_k) * 2;

    const uint32_t smbase = smem_u32(&sm[0][0][0]);
    const uint32_t ARR = 128 * 24 * 2;

    float acc[2][8][4];
#pragma unroll
    for (int mt = 0; mt < 2; mt++)
#pragma unroll
        for (int nt = 0; nt < 8; nt++)
#pragma unroll
            for (int j = 0; j < 4; j++) acc[mt][nt][j] = 0.f;

    for (int kt = 0; kt < NT; kt++) {
        const int cur = kt & 1;
        if (kt + 1 < NT) {
            const int nx = cur ^ 1;
            const long kb = (long)(kt + 1) << 4;
            cp16(&sm[nx][0][soff], Ah + aoff + kb);
            cp16(&sm[nx][1][soff], Al + aoff + kb);
            cp16(&sm[nx][2][soff], Bh + boff + kb);
            cp16(&sm[nx][3][soff], Bl + boff + kb);
            cp_commit();
            cp_wait<1>();
        } else {
            cp_wait<0>();
        }
        __syncthreads();

        const uint32_t bAh = smbase + (cur * 4 + 0) * ARR;
        const uint32_t bAl = smbase + (cur * 4 + 1) * ARR;
        const uint32_t bBh = smbase + (cur * 4 + 2) * ARR;
        const uint32_t bBl = smbase + (cur * 4 + 3) * ARR;

        uint32_t ah[2][4], al[2][4], bh[4][4], bl[4][4];
#pragma unroll
        for (int mt = 0; mt < 2; mt++) {
            ldsm4(ah[mt], bAh + aoffs[mt]);
            ldsm4(al[mt], bAl + aoffs[mt]);
        }
#pragma unroll
        for (int p = 0; p < 4; p++) {
            ldsm4(bh[p], bBh + boffs[p]);
            ldsm4(bl[p], bBl + boffs[p]);
        }

#pragma unroll
        for (int mt = 0; mt < 2; mt++)
#pragma unroll
            for (int nt = 0; nt < 8; nt++)
                mma_bf(acc[mt][nt], ah[mt],
                       bh[nt >> 1][(nt & 1) * 2], bh[nt >> 1][(nt & 1) * 2 + 1]);
#pragma unroll
        for (int mt = 0; mt < 2; mt++)
#pragma unroll
            for (int nt = 0; nt < 8; nt++)
                mma_bf(acc[mt][nt], ah[mt],
                       bl[nt >> 1][(nt & 1) * 2], bl[nt >> 1][(nt & 1) * 2 + 1]);
#pragma unroll
        for (int mt = 0; mt < 2; mt++)
#pragma unroll
            for (int nt = 0; nt < 8; nt++)
                mma_bf(acc[mt][nt], al[mt],
                       bh[nt >> 1][(nt & 1) * 2], bh[nt >> 1][(nt & 1) * 2 + 1]);
        __syncthreads();
    }

#pragma unroll
    for (int mt = 0; mt < 2; mt++) {
        int r0 = m0 + wm + mt * 16 + (lane >> 2);
#pragma unroll
        for (int nt = 0; nt < 8; nt++) {
            int cc = n0 + wn + nt * 8 + (lane & 3) * 2;
            float* c = acc[mt][nt];
            if (r0 < M) {
                float2 o; o.x = c[0]; o.y = c[1];
                *(float2*)(P + (long)r0 * N + cc) = o;
            }
            if (r0 + 8 < M) {
                float2 o; o.x = c[2]; o.y = c[3];
                *(float2*)(P + (long)(r0 + 8) * N + cc) = o;
            }
        }
    }
}

// ---------------- kv reduce ----------------
__global__ void kvred_kernel(const float* __restrict__ P, const float* __restrict__ bias,
                             float* __restrict__ out) {
    int i4 = blockIdx.x * 256 + threadIdx.x;
    if (i4 >= 65536) return;
    const float4* P4 = (const float4*)P;
    float4 a = P4[i4];
#pragma unroll
    for (int s = 1; s < 8; s++) {
        float4 b = P4[s * 65536 + i4];
        a.x += b.x; a.y += b.y; a.z += b.z; a.w += b.w;
    }
    int n = (i4 * 4) & 4095;
    const float4 bv = *(const float4*)(bias + n);
    a.x += bv.x; a.y += bv.y; a.z += bv.z; a.w += bv.w;
    ((float4*)out)[i4] = a;
}

// ---------------- compete logits: cw staged in dynamic smem ----------------
__global__ void compete_kernel(const float* __restrict__ x, const float* __restrict__ cw,
                               const float* __restrict__ cb, const float* __restrict__ npw,
                               float* __restrict__ logits) {
    extern __shared__ float scw[];
    int tid = threadIdx.x;
    for (int e = tid; e < SS * DD; e += 512) scw[e] = cw[e];
    __syncthreads();
    int warp = tid >> 5, lane = tid & 31;
#pragma unroll
    for (int r = 0; r < 2; r++) {
        int row = blockIdx.x * 32 + warp * 2 + r;
        const float* xr = x + (long)row * DD;
        float ss = 0.f;
        float acc[SS];
#pragma unroll
        for (int s = 0; s < SS; s++) acc[s] = 0.f;
        for (int j = lane; j < DD; j += 32) {
            float xv = xr[j];
            ss += xv * xv;
            float xn = xv * npw[j];
#pragma unroll
            for (int s = 0; s < SS; s++) acc[s] += xn * scw[s * DD + j];
        }
#pragma unroll
        for (int o = 16; o; o >>= 1) ss += __shfl_xor_sync(0xffffffffu, ss, o);
#pragma unroll
        for (int s = 0; s < SS; s++) {
#pragma unroll
            for (int o = 16; o; o >>= 1) acc[s] += __shfl_xor_sync(0xffffffffu, acc[s], o);
        }
        float rinv = rsqrtf(ss * (1.f / DD) + EPSF);
        float myv = 0.f;
#pragma unroll
        for (int s = 0; s < SS; s++) if (lane == s) myv = acc[s];
        if (lane < SS) logits[(long)row * SS + lane] = myv * rinv + cb[lane];
    }
}

// ---------------- top-4 + softmax weights (tree merge) ----------------
__device__ __forceinline__ bool tk_better(float v1, int i1, float v2, int i2) {
    return (v1 > v2) || (v1 == v2 && i1 < i2);
}
__device__ __forceinline__ void tk_insert(float* v, int* id, float nv, int ni) {
    if (tk_better(nv, ni, v[KK - 1], id[KK - 1])) {
        v[KK - 1] = nv; id[KK - 1] = ni;
#pragma unroll
        for (int j = KK - 1; j > 0; j--) {
            if (tk_better(v[j], id[j], v[j - 1], id[j - 1])) {
                float tv = v[j]; v[j] = v[j - 1]; v[j - 1] = tv;
                int ti = id[j]; id[j] = id[j - 1]; id[j - 1] = ti;
            }
        }
    }
}

__global__ void topk_kernel(const float* __restrict__ logits, int* __restrict__ idxo,
                            float* __restrict__ wgto) {
    int bs = blockIdx.x;
    int b = bs / SS, s = bs % SS;
    int tid = threadIdx.x;
    float v[KK]; int id[KK];
#pragma unroll
    for (int k = 0; k < KK; k++) { v[k] = -3.4e38f; id[k] = 0x7fffffff; }
    for (int l = tid; l < LL; l += 256)
        tk_insert(v, id, logits[((long)b * LL + l) * SS + s], l);

    __shared__ float sv[256 * KK];
    __shared__ int   si[256 * KK];
#pragma unroll
    for (int k = 0; k < KK; k++) { sv[tid * KK + k] = v[k]; si[tid * KK + k] = id[k]; }

    for (int step = 128; step >= 1; step >>= 1) {
        __syncthreads();
        if (tid < step) {
            float* av = &sv[tid * KK]; int* ai = &si[tid * KK];
            float mv[KK]; int mi[KK];
#pragma unroll
            for (int k = 0; k < KK; k++) { mv[k] = av[k]; mi[k] = ai[k]; }
#pragma unroll
            for (int k = 0; k < KK; k++)
                tk_insert(mv, mi, sv[(tid + step) * KK + k], si[(tid + step) * KK + k]);
#pragma unroll
            for (int k = 0; k < KK; k++) { av[k] = mv[k]; ai[k] = mi[k]; }
        }
    }
    __syncthreads();
    if (tid == 0) {
        float m = sv[0];
        float e[KK]; float sum = 0.f;
#pragma unroll
        for (int k = 0; k < KK; k++) { e[k] = expf(sv[k] - m); sum += e[k]; }
        float inv = 1.f / sum;
#pragma unroll
        for (int k = 0; k < KK; k++) { wgto[bs * KK + k] = e[k] * inv; idxo[bs * KK + k] = si[k]; }
    }
}

// ---------------- weighted gather -> bf16 hi/lo ----------------
__global__ void gatherw_kernel(const float* __restrict__ x, const int* __restrict__ idx,
                               const float* __restrict__ wgt,
                               __nv_bfloat16* __restrict__ xwh, __nv_bfloat16* __restrict__ xwl) {
    int bs = blockIdx.x;
    int b = bs / SS;
    const float* r0 = x + ((long)b * LL + idx[bs * KK + 0]) * DD;
    const float* r1 = x + ((long)b * LL + idx[bs * KK + 1]) * DD;
    const float* r2 = x + ((long)b * LL + idx[bs * KK + 2]) * DD;
    const float* r3 = x + ((long)b * LL + idx[bs * KK + 3]) * DD;
    float w0 = wgt[bs * KK + 0], w1 = wgt[bs * KK + 1];
    float w2 = wgt[bs * KK + 2], w3 = wgt[bs * KK + 3];
    for (int d = threadIdx.x; d < DD; d += blockDim.x) {
        float v = w0 * r0[d] + w1 * r1[d] + w2 * r2[d] + w3 * r3[d];
        __nv_bfloat16 h, lo;
        split1(v, h, lo);
        xwh[(long)bs * DD + d] = h;
        xwl[(long)bs * DD + d] = lo;
    }
}

// ---------------- ws update + rms ----------------
__global__ void ws_update_kernel(const float* __restrict__ P, const float* __restrict__ wgt,
                                 const float* __restrict__ wb, const float* __restrict__ npw,
                                 float* __restrict__ ws,
                                 __nv_bfloat16* __restrict__ wsh, __nv_bfloat16* __restrict__ wsl) {
    int bs = blockIdx.x;
    __shared__ float t[DD];
    __shared__ float red[256];
    float sumw = wgt[bs * KK + 0] + wgt[bs * KK + 1] + wgt[bs * KK + 2] + wgt[bs * KK + 3];
    const long MN = (long)BB * SS * DD;
    long rr = (long)bs * DD;
    float ssp = 0.f;
    for (int d = threadIdx.x; d < DD; d += 256) {
        float a = sumw * wb[d];
#pragma unroll
        for (int sp = 0; sp < 8; sp++) a += P[(long)sp * MN + rr + d];
        float v = ws[rr + d] + a;
        t[d] = v; ssp += v * v;
    }
    red[threadIdx.x] = ssp; __syncthreads();
    for (int st = 128; st; st >>= 1) {
        if (threadIdx.x < st) red[threadIdx.x] += red[threadIdx.x + st];
        __syncthreads();
    }
    float rinv = rsqrtf(red[0] * (1.f / DD) + EPSF);
    for (int d = threadIdx.x; d < DD; d += 256) {
        float v = t[d] * rinv * npw[d];
        ws[rr + d] = v;
        __nv_bfloat16 h, lo;
        split1(v, h, lo);
        wsh[rr + d] = h;
        wsl[rr + d] = lo;
    }
}

// ---------------- fold kk with wq: G[b,(h,s),d] -> bf16 hi/lo ----------------
__global__ __launch_bounds__(128) void gfold_kernel(const float* __restrict__ kv,
                                                    const float* __restrict__ wq,
                                                    __nv_bfloat16* __restrict__ Gh,
                                                    __nv_bfloat16* __restrict__ Gl) {
    int b = blockIdx.y / HH, h = blockIdx.y % HH;
    int d0 = blockIdx.x * 128;
    __shared__ float ks[SS][HD];
    __shared__ float wqs[HD][128 + 1];
    for (int e = threadIdx.x; e < SS * HD; e += 128) {
        int s = e >> 6, i = e & 63;
        ks[s][i] = kv[((long)b * SS + s) * (2 * DD) + h * HD + i];
    }
    for (int e = threadIdx.x; e < HD * 128; e += 128) {
        int i = e >> 7, c = e & 127;
        wqs[i][c] = wq[(long)(h * HD + i) * DD + d0 + c];
    }
    __syncthreads();
    int d = threadIdx.x;
    float acc[SS];
#pragma unroll
    for (int s = 0; s < SS; s++) acc[s] = 0.f;
#pragma unroll
    for (int i = 0; i < HD; i++) {
        float w = wqs[i][d];
#pragma unroll
        for (int s = 0; s < SS; s++) acc[s] += w * ks[s][i];
    }
#pragma unroll
    for (int s = 0; s < SS; s++) {
        long off = ((long)b * HH * SS + h * SS + s) * DD + d0 + d;
        __nv_bfloat16 hh, ll;
        split1(acc[s], hh, ll);
        Gh[off] = hh;
        Gl[off] = ll;
    }
}

// ---------------- sbias[b,h,s] ----------------
__global__ void sbias_kernel(const float* __restrict__ kv, const float* __restrict__ bq,
                             float* __restrict__ sbias) {
    int bh = blockIdx.x;
    int b = bh / HH, h = bh % HH;
    int lane = threadIdx.x;
    for (int s = 0; s < SS; s++) {
        float a = 0.f;
        for (int i = lane; i < HD; i += 32)
            a += bq[h * HD + i] * kv[((long)b * SS + s) * (2 * DD) + h * HD + i];
#pragma unroll
        for (int o = 16; o; o >>= 1) a += __shfl_xor_sync(0xffffffffu, a, o);
        if (lane == 0) sbias[(long)bh * SS + s] = a;
    }
}

// ---------------- fold vv with out_proj -> voT fp16 hi/lo ----------------
__global__ __launch_bounds__(128) void vo_kernel(const float* __restrict__ kv,
                                                 const float* __restrict__ wout,
                                                 __half* __restrict__ voTh,
                                                 __half* __restrict__ voTl) {
    int b = blockIdx.y / HH, h = blockIdx.y % HH;
    int d0 = blockIdx.x * 128;
    __shared__ float vs[SS][HD];
    __shared__ float wsm[128][HD + 1];
    for (int e = threadIdx.x; e < SS * HD; e += 128) {
        int s = e >> 6, i = e & 63;
        vs[s][i] = kv[((long)b * SS + s) * (2 * DD) + DD + h * HD + i];
    }
    for (int e = threadIdx.x; e < 128 * HD; e += 128) {
        int r = e >> 6, i = e & 63;
        wsm[r][i] = wout[(long)(d0 + r) * DD + h * HD + i];
    }
    __syncthreads();
    int d = threadIdx.x;
    float acc[SS];
#pragma unroll
    for (int s = 0; s < SS; s++) acc[s] = 0.f;
#pragma unroll
    for (int i = 0; i < HD; i++) {
        float w = wsm[d][i];
#pragma unroll
        for (int s = 0; s < SS; s++) acc[s] += w * vs[s][i];
    }
    long base = ((long)b * DD + d0 + d) * (HH * SS) + h * SS;
#pragma unroll
    for (int s = 0; s < SS; s++) {
        __half hh, ll;
        split1h(acc[s], hh, ll);
        voTh[base + s] = hh;
        voTl[base + s] = ll;
    }
}

// ---------------- x = rms(x + xb) -> fp32 out (+ bf16 hi/lo), float4 ----------------
__global__ void resid_rms_kernel(const float* __restrict__ xin, const float* __restrict__ xb,
                                 const float* __restrict__ npw, float* __restrict__ xout,
                                 __nv_bfloat16* __restrict__ xh, __nv_bfloat16* __restrict__ xl) {
    long row = blockIdx.x;
    __shared__ float t[DD];
    __shared__ float red[256];
    const float4* a4 = (const float4*)(xin + row * DD);
    const float4* c4 = (const float4*)(xb + row * DD);
    float4* t4 = (float4*)t;
    float ssp = 0.f;
#pragma unroll
    for (int q = 0; q < 2; q++) {
        int i4 = threadIdx.x + q * 256;
        float4 a = a4[i4], c = c4[i4];
        float4 v; v.x = a.x + c.x; v.y = a.y + c.y; v.z = a.z + c.z; v.w = a.w + c.w;
        t4[i4] = v;
        ssp += v.x * v.x + v.y * v.y + v.z * v.z + v.w * v.w;
    }
    red[threadIdx.x] = ssp; __syncthreads();
    for (int st = 128; st; st >>= 1) {
        if (threadIdx.x < st) red[threadIdx.x] += red[threadIdx.x + st];
        __syncthreads();
    }
    float rinv = rsqrtf(red[0] * (1.f / DD) + EPSF);
    const float4* w4 = (const float4*)npw;
    float4* o4 = (float4*)(xout + row * DD);
    __nv_bfloat162* h2 = (__nv_bfloat162*)(xh + row * DD);
    __nv_bfloat162* l2 = (__nv_bfloat162*)(xl + row * DD);
#pragma unroll
    for (int q = 0; q < 2; q++) {
        int i4 = threadIdx.x + q * 256;
        float4 v = t4[i4], w = w4[i4];
        v.x *= rinv * w.x; v.y *= rinv * w.y; v.z *= rinv * w.z; v.w *= rinv * w.w;
        o4[i4] = v;
        __nv_bfloat16 h[4], l[4];
        split1(v.x, h[0], l[0]); split1(v.y, h[1], l[1]);
        split1(v.z, h[2], l[2]); split1(v.w, h[3], l[3]);
        __nv_bfloat162 ph0; ph0.x = h[0]; ph0.y = h[1];
        __nv_bfloat162 ph1; ph1.x = h[2]; ph1.y = h[3];
        __nv_bfloat162 pl0; pl0.x = l[0]; pl0.y = l[1];
        __nv_bfloat162 pl1; pl1.x = l[2]; pl1.y = l[3];
        h2[i4 * 2] = ph0; h2[i4 * 2 + 1] = ph1;
        l2[i4 * 2] = pl0; l2[i4 * 2 + 1] = pl1;
    }
}

// ---------------- host launch ----------------
static inline void run_split(const float* src, __nv_bfloat16* hi, __nv_bfloat16* lo, long n) {
    long n4 = n >> 2;
    split4_kernel<<<(int)((n4 + 255) / 256), 256>>>(src, hi, lo, n4);
}

#define CW_SMEM (SS * DD * 4)

extern "C" void kernel_launch(void* const* d_in, const int* in_sizes, int n_in,
                              void* d_out, int out_size) {
    const float* x_in       = (const float*)d_in[0];
    const float* workspace  = (const float*)d_in[1];
    const float* compete_w  = (const float*)d_in[2];
    const float* compete_b  = (const float*)d_in[3];
    const float* write_w    = (const float*)d_in[4];
    const float* write_b    = (const float*)d_in[5];
    const float* in_proj_w  = (const float*)d_in[6];
    const float* in_proj_b  = (const float*)d_in[7];
    const float* out_proj_w = (const float*)d_in[8];
    const float* out_proj_b = (const float*)d_in[9];
    const float* norm_pre_w  = (const float*)d_in[12];
    const float* norm_post_w = (const float*)d_in[13];

    cudaFuncSetAttribute(compete_kernel, cudaFuncAttributeMaxDynamicSharedMemorySize, CW_SMEM);

    void *p;
    float *px, *pxb, *plog, *pws, *pkv, *ppart, *pwgt, *psb;
    int *pidx;
    __nv_bfloat16 *pxh, *pxl, *pwkvh, *pwkvl, *pwwh, *pwwl, *pGh, *pGl, *pwsh, *pwsl, *pxwh, *pxwl;
    __half *patth, *pvoTh, *pvoTl;
    cudaGetSymbolAddress(&p, g_x);     px   = (float*)p;
    cudaGetSymbolAddress(&p, g_xb);    pxb  = (float*)p;
    cudaGetSymbolAddress(&p, g_logits); plog = (float*)p;
    cudaGetSymbolAddress(&p, g_ws);    pws  = (float*)p;
    cudaGetSymbolAddress(&p, g_kv);    pkv  = (float*)p;
    cudaGetSymbolAddress(&p, g_part);  ppart = (float*)p;
    cudaGetSymbolAddress(&p, g_wgt);   pwgt = (float*)p;
    cudaGetSymbolAddress(&p, g_sbias); psb  = (float*)p;
    cudaGetSymbolAddress(&p, g_idx);   pidx = (int*)p;
    cudaGetSymbolAddress(&p, g_xh);    pxh  = (__nv_bfloat16*)p;
    cudaGetSymbolAddress(&p, g_xl);    pxl  = (__nv_bfloat16*)p;
    cudaGetSymbolAddress(&p, g_wkvh);  pwkvh = (__nv_bfloat16*)p;
    cudaGetSymbolAddress(&p, g_wkvl);  pwkvl = (__nv_bfloat16*)p;
    cudaGetSymbolAddress(&p, g_wwh);   pwwh = (__nv_bfloat16*)p;
    cudaGetSymbolAddress(&p, g_wwl);   pwwl = (__nv_bfloat16*)p;
    cudaGetSymbolAddress(&p, g_Gh);    pGh  = (__nv_bfloat16*)p;
    cudaGetSymbolAddress(&p, g_Gl);    pGl  = (__nv_bfloat16*)p;
    cudaGetSymbolAddress(&p, g_wsh);   pwsh = (__nv_bfloat16*)p;
    cudaGetSymbolAddress(&p, g_wsl);   pwsl = (__nv_bfloat16*)p;
    cudaGetSymbolAddress(&p, g_xwh);   pxwh = (__nv_bfloat16*)p;
    cudaGetSymbolAddress(&p, g_xwl);   pxwl = (__nv_bfloat16*)p;
    cudaGetSymbolAddress(&p, g_atth);  patth = (__half*)p;
    cudaGetSymbolAddress(&p, g_voTh);  pvoTh = (__half*)p;
    cudaGetSymbolAddress(&p, g_voTl);  pvoTl = (__half*)p;

    // init: x <- input (fp32 + hi/lo), ws <- broadcast(workspace)
    {
        long n4 = (long)BB * LL * DD / 4;
        copysplit_kernel<<<(int)((n4 + 255) / 256), 256>>>(x_in, px, pxh, pxl, n4);
        init_ws_kernel<<<BB * SS, 256>>>(workspace, pws);
    }
    // weight splits (once per launch); wq stays fp32 (used only in gfold)
    run_split(in_proj_w + (long)DD * DD, pwkvh, pwkvl, (long)2 * DD * DD);
    run_split(write_w, pwwh, pwwl, (long)DD * DD);

    for (int it = 0; it < NB; it++) {
        // 1. compete logits (cw in smem)
        compete_kernel<<<BB * LL / 32, 512, CW_SMEM>>>(px, compete_w, compete_b, norm_pre_w, plog);
        // 2. top-k + softmax weights (tree merge)
        topk_kernel<<<BB * SS, 256>>>(plog, pidx, pwgt);
        // 3. weighted gather: xw = sum_k wgt_k x_k (64 rows)
        gatherw_kernel<<<BB * SS, 256>>>(px, pidx, pwgt, pxwh, pxwl);
        // 4. write projection (64 x 2048 x 2048), split-K=8 -> partials
        {
            dim3 grid(DD / 128, 1, 8);
            gemm3p_kernel<<<grid, 256>>>(pxwh, pxwl, pwwh, pwwl, ppart,
                                         BB * SS, DD, DD, DD / 8);
        }
        // 5. workspace update + rms (+hi/lo), reduces partials inline
        ws_update_kernel<<<BB * SS, 256>>>(ppart, pwgt, write_b, norm_post_w, pws, pwsh, pwsl);
        // 6. kk|vv projection (64 x 4096 x 2048), split-K=8 -> partials -> reduce
        {
            dim3 grid((2 * DD) / 128, 1, 8);
            gemm3p_kernel<<<grid, 256>>>(pwsh, pwsl, pwkvh, pwkvl, ppart,
                                         BB * SS, 2 * DD, DD, DD / 8);
            kvred_kernel<<<256, 256>>>(ppart, in_proj_b + DD, pkv);
        }
        // 7. fold kk with wq -> G ; sbias
        {
            dim3 grid(DD / 128, BB * HH, 1);
            gfold_kernel<<<grid, 128>>>(pkv, in_proj_w, pGh, pGl);
            sbias_kernel<<<BB * HH, 32>>>(pkv, in_proj_b, psb);
        }
        // 8. fold vv with out_proj -> voT fp16 hi/lo
        {
            dim3 grid(DD / 128, BB * HH, 1);
            vo_kernel<<<grid, 128>>>(pkv, out_proj_w, pvoTh, pvoTl);
        }
        // 9. scores GEMM (bf16x3) + fused softmax -> att fp16 (hi only)
        {
            dim3 grid(HH * SS / 128, LL / 128, BB);
            gemm3s_kernel<<<grid, 256>>>(pxh, pxl, pGh, pGl, psb, patth,
                                         DD, (long)LL * DD, (long)HH * SS * DD);
        }
        // 10. x_b = att @ (voTh+voTl)^T + out_proj_b — 2-term fp16 GEMM, f32 acc
        {
            dim3 grid(DD / 128, LL / 128, BB);
            gemm2_kernel<<<grid, 256>>>(patth, pvoTh, pvoTl, out_proj_b, pxb,
                                        LL, DD, HH * SS,
                                        (long)LL * HH * SS, (long)DD * HH * SS,
                                        (long)LL * DD);
        }
        // 11. x = rms(x + x_b) (+hi/lo); last round writes d_out
        float* xdst = (it == NB - 1) ? (float*)d_out : px;
        resid_rms_kernel<<<BB * LL, 256>>>(px, pxb, norm_post_w, xdst, pxh, pxl);
    }
}

// round 16
// speedup vs baseline: 1.1907x; 1.0822x over previous
#include <cuda_runtime.h>
#include <cuda_bf16.h>
#include <cuda_fp16.h>
#include <cstdint>

// ---------------- problem constants ----------------
#define BB 4
#define LL 2048
#define DD 2048
#define SS 16
#define KK 4
#define NB 2
#define HH 32
#define HD 64
#define EPSF 1e-6f

// ---------------- device scratch (no allocs allowed) ----------------
__device__ float g_x[BB * LL * DD];
__device__ float g_xb[BB * LL * DD];
__device__ float g_logits[BB * LL * SS];
__device__ float g_ws[BB * SS * DD];
__device__ float g_kv[BB * SS * 2 * DD];
__device__ float g_part[8 * 64 * 4096];       // split-K partials
__device__ float g_wgt[BB * SS * KK];
__device__ float g_sbias[BB * HH * SS];
__device__ int   g_idx[BB * SS * KK];

// bf16 hi/lo split operands for the small split-K projections
__device__ __nv_bfloat16 g_wkvh[2 * DD * DD],  g_wkvl[2 * DD * DD];
__device__ __nv_bfloat16 g_wwh[DD * DD],       g_wwl[DD * DD];
__device__ __nv_bfloat16 g_wsh[BB * SS * DD],  g_wsl[BB * SS * DD];
__device__ __nv_bfloat16 g_xwh[BB * SS * DD],  g_xwl[BB * SS * DD];
// fp16 operands for the attention path (11-bit mantissa => 2-term GEMMs safe)
__device__ __half g_xh[BB * LL * DD];                       // x, fp16 (hi only)
__device__ __half g_Gh[BB * HH * SS * DD], g_Gl[BB * HH * SS * DD];
__device__ __half g_atth[BB * LL * HH * SS];
__device__ __half g_voTh[BB * DD * HH * SS], g_voTl[BB * DD * HH * SS];

// ---------------- PTX helpers ----------------
__device__ __forceinline__ void cp16(void* sdst, const void* gsrc) {
    uint32_t d = (uint32_t)__cvta_generic_to_shared(sdst);
    asm volatile("cp.async.cg.shared.global [%0], [%1], 16;\n" :: "r"(d), "l"(gsrc));
}
__device__ __forceinline__ void cp_commit() { asm volatile("cp.async.commit_group;\n"); }
template <int N> __device__ __forceinline__ void cp_wait() {
    asm volatile("cp.async.wait_group %0;\n" :: "n"(N));
}
__device__ __forceinline__ void ldsm4(uint32_t* r, uint32_t saddr) {
    asm volatile("ldmatrix.sync.aligned.m8n8.x4.shared.b16 {%0,%1,%2,%3}, [%4];\n"
                 : "=r"(r[0]), "=r"(r[1]), "=r"(r[2]), "=r"(r[3]) : "r"(saddr));
}
// bf16 inputs, f32 accumulator
__device__ __forceinline__ void mma_bf(float* c, const uint32_t* a, uint32_t b0, uint32_t b1) {
    asm volatile("mma.sync.aligned.m16n8k16.row.col.f32.bf16.bf16.f32 "
                 "{%0,%1,%2,%3}, {%4,%5,%6,%7}, {%8,%9}, {%0,%1,%2,%3};\n"
                 : "+f"(c[0]), "+f"(c[1]), "+f"(c[2]), "+f"(c[3])
                 : "r"(a[0]), "r"(a[1]), "r"(a[2]), "r"(a[3]), "r"(b0), "r"(b1));
}
// fp16 inputs, f32 accumulator
__device__ __forceinline__ void mma_fp(float* c, const uint32_t* a, uint32_t b0, uint32_t b1) {
    asm volatile("mma.sync.aligned.m16n8k16.row.col.f32.f16.f16.f32 "
                 "{%0,%1,%2,%3}, {%4,%5,%6,%7}, {%8,%9}, {%0,%1,%2,%3};\n"
                 : "+f"(c[0]), "+f"(c[1]), "+f"(c[2]), "+f"(c[3])
                 : "r"(a[0]), "r"(a[1]), "r"(a[2]), "r"(a[3]), "r"(b0), "r"(b1));
}
__device__ __forceinline__ void split1(float v, __nv_bfloat16& h, __nv_bfloat16& l) {
    h = __float2bfloat16(v);
    l = __float2bfloat16(v - __bfloat162float(h));
}
__device__ __forceinline__ void split1h(float v, __half& h, __half& l) {
    h = __float2half_rn(v);
    l = __float2half_rn(v - __half2float(h));
}
__device__ __forceinline__ uint32_t smem_u32(const void* p) {
    return (uint32_t)__cvta_generic_to_shared(p);
}

// ---------------- splits ----------------
__global__ void split4_kernel(const float* __restrict__ src, __nv_bfloat16* __restrict__ hi,
                              __nv_bfloat16* __restrict__ lo, long n4) {
    long i = (long)blockIdx.x * blockDim.x + threadIdx.x;
    if (i >= n4) return;
    float4 v = ((const float4*)src)[i];
    __nv_bfloat16 h[4], l[4];
    split1(v.x, h[0], l[0]); split1(v.y, h[1], l[1]);
    split1(v.z, h[2], l[2]); split1(v.w, h[3], l[3]);
    __nv_bfloat162 ph0; ph0.x = h[0]; ph0.y = h[1];
    __nv_bfloat162 ph1; ph1.x = h[2]; ph1.y = h[3];
    __nv_bfloat162 pl0; pl0.x = l[0]; pl0.y = l[1];
    __nv_bfloat162 pl1; pl1.x = l[2]; pl1.y = l[3];
    ((__nv_bfloat162*)hi)[2 * i]     = ph0;
    ((__nv_bfloat162*)hi)[2 * i + 1] = ph1;
    ((__nv_bfloat162*)lo)[2 * i]     = pl0;
    ((__nv_bfloat162*)lo)[2 * i + 1] = pl1;
}

// x init: fp32 copy + single fp16
__global__ void copysplit_kernel(const float* __restrict__ src, float* __restrict__ dst,
                                 __half* __restrict__ hi, long n4) {
    long i = (long)blockIdx.x * blockDim.x + threadIdx.x;
    if (i >= n4) return;
    float4 v = ((const float4*)src)[i];
    ((float4*)dst)[i] = v;
    ((__half2*)hi)[2 * i]     = __halves2half2(__float2half_rn(v.x), __float2half_rn(v.y));
    ((__half2*)hi)[2 * i + 1] = __halves2half2(__float2half_rn(v.z), __float2half_rn(v.w));
}

__global__ void init_ws_kernel(const float* __restrict__ wsrc, float* __restrict__ ws) {
    int bs = blockIdx.x;
    int s = bs % SS;
    for (int d = threadIdx.x; d < DD; d += blockDim.x)
        ws[(long)bs * DD + d] = wsrc[(long)s * DD + d];
}

// ---------------- 2-term fp16 GEMM for xb: C = A @ (Bh+Bl)^T + bias ----------------
__global__ __launch_bounds__(256) void gemm2_kernel(
    const __half* __restrict__ A,
    const __half* __restrict__ Bh, const __half* __restrict__ Bl,
    const float* __restrict__ bias, float* __restrict__ C,
    int M, int N, int K, long bsA, long bsB, long bsC) {
    A  += (long)blockIdx.z * bsA;
    Bh += (long)blockIdx.z * bsB; Bl += (long)blockIdx.z * bsB;
    C  += (long)blockIdx.z * bsC;

    __shared__ __align__(16) __half sm[2][3][128 * 24];

    const int tid = threadIdx.x;
    const int m0 = blockIdx.y * 128, n0 = blockIdx.x * 128;

    const int lrow = tid >> 1, lhalf = tid & 1;
    const long aoff = (long)(m0 + lrow) * K + lhalf * 8;
    const long boff = (long)(n0 + lrow) * K + lhalf * 8;
    const uint32_t soff = lrow * 24 + lhalf * 8;

    const int NT = K >> 4;

    cp16(&sm[0][0][soff], A + aoff);
    cp16(&sm[0][1][soff], Bh + boff);
    cp16(&sm[0][2][soff], Bl + boff);
    cp_commit();

    const int lane = tid & 31, warp = tid >> 5;
    const int wm = (warp & 3) * 32;
    const int wn = (warp >> 2) * 64;

    uint32_t a_row = wm + (lane & 7) + ((lane >> 3) & 1) * 8;
    uint32_t a_k   = (lane >> 4) * 8;
    uint32_t aoffs[2];
    aoffs[0] = ((a_row) * 24 + a_k) * 2;
    aoffs[1] = ((a_row + 16) * 24 + a_k) * 2;
    uint32_t b_row = wn + (lane & 7) + ((lane >> 4) ? 8 : 0);
    uint32_t b_k   = ((lane >> 3) & 1) * 8;
    uint32_t boffs[4];
#pragma unroll
    for (int p = 0; p < 4; p++) boffs[p] = ((b_row + p * 16) * 24 + b_k) * 2;

    const uint32_t smbase = smem_u32(&sm[0][0][0]);
    const uint32_t ARR = 128 * 24 * 2;

    float acc[2][8][4];
#pragma unroll
    for (int mt = 0; mt < 2; mt++)
#pragma unroll
        for (int nt = 0; nt < 8; nt++)
#pragma unroll
            for (int j = 0; j < 4; j++) acc[mt][nt][j] = 0.f;

    for (int kt = 0; kt < NT; kt++) {
        const int cur = kt & 1;
        if (kt + 1 < NT) {
            const int nx = cur ^ 1;
            const long kb = (long)(kt + 1) << 4;
            cp16(&sm[nx][0][soff], A + aoff + kb);
            cp16(&sm[nx][1][soff], Bh + boff + kb);
            cp16(&sm[nx][2][soff], Bl + boff + kb);
            cp_commit();
            cp_wait<1>();
        } else {
            cp_wait<0>();
        }
        __syncthreads();

        const uint32_t bA  = smbase + (cur * 3 + 0) * ARR;
        const uint32_t bBh = smbase + (cur * 3 + 1) * ARR;
        const uint32_t bBl = smbase + (cur * 3 + 2) * ARR;

        uint32_t ah[2][4], bh[4][4], bl[4][4];
#pragma unroll
        for (int mt = 0; mt < 2; mt++) ldsm4(ah[mt], bA + aoffs[mt]);
#pragma unroll
        for (int p = 0; p < 4; p++) {
            ldsm4(bh[p], bBh + boffs[p]);
            ldsm4(bl[p], bBl + boffs[p]);
        }

#pragma unroll
        for (int mt = 0; mt < 2; mt++)
#pragma unroll
            for (int nt = 0; nt < 8; nt++)
                mma_fp(acc[mt][nt], ah[mt],
                       bh[nt >> 1][(nt & 1) * 2], bh[nt >> 1][(nt & 1) * 2 + 1]);
#pragma unroll
        for (int mt = 0; mt < 2; mt++)
#pragma unroll
            for (int nt = 0; nt < 8; nt++)
                mma_fp(acc[mt][nt], ah[mt],
                       bl[nt >> 1][(nt & 1) * 2], bl[nt >> 1][(nt & 1) * 2 + 1]);
        __syncthreads();
    }

#pragma unroll
    for (int mt = 0; mt < 2; mt++) {
        int r0 = m0 + wm + mt * 16 + (lane >> 2);
#pragma unroll
        for (int nt = 0; nt < 8; nt++) {
            int cc = n0 + wn + nt * 8 + (lane & 3) * 2;
            float b0v = bias[cc], b1v = bias[cc + 1];
            float* c = acc[mt][nt];
            float2 o0; o0.x = c[0] + b0v; o0.y = c[1] + b1v;
            *(float2*)(C + (long)r0 * N + cc) = o0;
            float2 o1; o1.x = c[2] + b0v; o1.y = c[3] + b1v;
            *(float2*)(C + (long)(r0 + 8) * N + cc) = o1;
        }
    }
}

// ---------------- 2-term fp16 scores GEMM + fused softmax -> fp16 att ----------------
// A = x fp16 (hi only), B = G fp16 hi/lo. Terms: A*Bh + A*Bl, both f32 acc.
__global__ __launch_bounds__(256) void gemm2s_kernel(
    const __half* __restrict__ A,
    const __half* __restrict__ Bh, const __half* __restrict__ Bl,
    const float* __restrict__ sbias,
    __half* __restrict__ atth,
    int K, long bsA, long bsB) {
    const int b = blockIdx.z;
    A  += (long)b * bsA;
    Bh += (long)b * bsB; Bl += (long)b * bsB;
    const float* sb = sbias + (long)b * (HH * SS);

    __shared__ __align__(16) __half sm[2][3][128 * 24];

    const int tid = threadIdx.x;
    const int m0 = blockIdx.y * 128, n0 = blockIdx.x * 128;

    const int lrow = tid >> 1, lhalf = tid & 1;
    const long aoff = (long)(m0 + lrow) * K + lhalf * 8;
    const long boff = (long)(n0 + lrow) * K + lhalf * 8;
    const uint32_t soff = lrow * 24 + lhalf * 8;

    const int NT = K >> 4;

    cp16(&sm[0][0][soff], A + aoff);
    cp16(&sm[0][1][soff], Bh + boff);
    cp16(&sm[0][2][soff], Bl + boff);
    cp_commit();

    const int lane = tid & 31, warp = tid >> 5;
    const int wm = (warp & 3) * 32;
    const int wn = (warp >> 2) * 64;

    uint32_t a_row = wm + (lane & 7) + ((lane >> 3) & 1) * 8;
    uint32_t a_k   = (lane >> 4) * 8;
    uint32_t aoffs[2];
    aoffs[0] = ((a_row) * 24 + a_k) * 2;
    aoffs[1] = ((a_row + 16) * 24 + a_k) * 2;
    uint32_t b_row = wn + (lane & 7) + ((lane >> 4) ? 8 : 0);
    uint32_t b_k   = ((lane >> 3) & 1) * 8;
    uint32_t boffs[4];
#pragma unroll
    for (int p = 0; p < 4; p++) boffs[p] = ((b_row + p * 16) * 24 + b_k) * 2;

    const uint32_t smbase = smem_u32(&sm[0][0][0]);
    const uint32_t ARR = 128 * 24 * 2;

    float acc[2][8][4];
#pragma unroll
    for (int mt = 0; mt < 2; mt++)
#pragma unroll
        for (int nt = 0; nt < 8; nt++)
#pragma unroll
            for (int j = 0; j < 4; j++) acc[mt][nt][j] = 0.f;

    for (int kt = 0; kt < NT; kt++) {
        const int cur = kt & 1;
        if (kt + 1 < NT) {
            const int nx = cur ^ 1;
            const long kb = (long)(kt + 1) << 4;
            cp16(&sm[nx][0][soff], A + aoff + kb);
            cp16(&sm[nx][1][soff], Bh + boff + kb);
            cp16(&sm[nx][2][soff], Bl + boff + kb);
            cp_commit();
            cp_wait<1>();
        } else {
            cp_wait<0>();
        }
        __syncthreads();

        const uint32_t bA  = smbase + (cur * 3 + 0) * ARR;
        const uint32_t bBh = smbase + (cur * 3 + 1) * ARR;
        const uint32_t bBl = smbase + (cur * 3 + 2) * ARR;

        uint32_t ah[2][4], bh[4][4], bl[4][4];
#pragma unroll
        for (int mt = 0; mt < 2; mt++) ldsm4(ah[mt], bA + aoffs[mt]);
#pragma unroll
        for (int p = 0; p < 4; p++) {
            ldsm4(bh[p], bBh + boffs[p]);
            ldsm4(bl[p], bBl + boffs[p]);
        }

#pragma unroll
        for (int mt = 0; mt < 2; mt++)
#pragma unroll
            for (int nt = 0; nt < 8; nt++)
                mma_fp(acc[mt][nt], ah[mt],
                       bh[nt >> 1][(nt & 1) * 2], bh[nt >> 1][(nt & 1) * 2 + 1]);
#pragma unroll
        for (int mt = 0; mt < 2; mt++)
#pragma unroll
            for (int nt = 0; nt < 8; nt++)
                mma_fp(acc[mt][nt], ah[mt],
                       bl[nt >> 1][(nt & 1) * 2], bl[nt >> 1][(nt & 1) * 2 + 1]);
        __syncthreads();
    }

    // fused softmax epilogue over 16-col head groups (quad shfl) -> fp16 att
#pragma unroll
    for (int mt = 0; mt < 2; mt++) {
        int r0 = m0 + wm + mt * 16 + (lane >> 2);
#pragma unroll
        for (int half = 0; half < 2; half++) {
            int row = r0 + half * 8;
            long obase = ((long)b * LL + row) * (HH * SS) + n0;
#pragma unroll
            for (int g = 0; g < 4; g++) {
                int c0 = wn + (2 * g) * 8 + (lane & 3) * 2;
                int c1 = wn + (2 * g + 1) * 8 + (lane & 3) * 2;
                float x0 = (acc[mt][2 * g][half * 2 + 0]     + sb[n0 + c0])     * 0.125f;
                float x1 = (acc[mt][2 * g][half * 2 + 1]     + sb[n0 + c0 + 1]) * 0.125f;
                float x2 = (acc[mt][2 * g + 1][half * 2 + 0] + sb[n0 + c1])     * 0.125f;
                float x3 = (acc[mt][2 * g + 1][half * 2 + 1] + sb[n0 + c1 + 1]) * 0.125f;
                float mx = fmaxf(fmaxf(x0, x1), fmaxf(x2, x3));
                mx = fmaxf(mx, __shfl_xor_sync(0xffffffffu, mx, 1));
                mx = fmaxf(mx, __shfl_xor_sync(0xffffffffu, mx, 2));
                float e0 = expf(x0 - mx), e1 = expf(x1 - mx);
                float e2 = expf(x2 - mx), e3 = expf(x3 - mx);
                float s = e0 + e1 + e2 + e3;
                s += __shfl_xor_sync(0xffffffffu, s, 1);
                s += __shfl_xor_sync(0xffffffffu, s, 2);
                float inv = 1.f / s;
                *(__half2*)(atth + obase + c0) =
                    __halves2half2(__float2half_rn(e0 * inv), __float2half_rn(e1 * inv));
                *(__half2*)(atth + obase + c1) =
                    __halves2half2(__float2half_rn(e2 * inv), __float2half_rn(e3 * inv));
            }
        }
    }
}

// ---------------- split-K bf16x3 GEMM: partial C (no bias) ----------------
__global__ __launch_bounds__(256) void gemm3p_kernel(
    const __nv_bfloat16* __restrict__ Ah, const __nv_bfloat16* __restrict__ Al,
    const __nv_bfloat16* __restrict__ Bh, const __nv_bfloat16* __restrict__ Bl,
    float* __restrict__ P, int M, int N, int K, int kLen) {
    const int ksplit = blockIdx.z;
    const int k0base = ksplit * kLen;
    P += (long)ksplit * M * N;

    __shared__ __align__(16) __nv_bfloat16 sm[2][4][128 * 24];

    const int tid = threadIdx.x;
    const int m0 = blockIdx.y * 128, n0 = blockIdx.x * 128;

    const int lrow = tid >> 1, lhalf = tid & 1;
    int arow = m0 + lrow; if (arow >= M) arow = M - 1;
    int brow = n0 + lrow; if (brow >= N) brow = N - 1;
    const long aoff = (long)arow * K + k0base + lhalf * 8;
    const long boff = (long)brow * K + k0base + lhalf * 8;
    const uint32_t soff = lrow * 24 + lhalf * 8;

    const int NT = kLen >> 4;

    cp16(&sm[0][0][soff], Ah + aoff);
    cp16(&sm[0][1][soff], Al + aoff);
    cp16(&sm[0][2][soff], Bh + boff);
    cp16(&sm[0][3][soff], Bl + boff);
    cp_commit();

    const int lane = tid & 31, warp = tid >> 5;
    const int wm = (warp & 3) * 32;
    const int wn = (warp >> 2) * 64;

    uint32_t a_row = wm + (lane & 7) + ((lane >> 3) & 1) * 8;
    uint32_t a_k   = (lane >> 4) * 8;
    uint32_t aoffs[2];
    aoffs[0] = ((a_row) * 24 + a_k) * 2;
    aoffs[1] = ((a_row + 16) * 24 + a_k) * 2;
    uint32_t b_row = wn + (lane & 7) + ((lane >> 4) ? 8 : 0);
    uint32_t b_k   = ((lane >> 3) & 1) * 8;
    uint32_t boffs[4];
#pragma unroll
    for (int p = 0; p < 4; p++) boffs[p] = ((b_row + p * 16) * 24 + b_k) * 2;

    const uint32_t smbase = smem_u32(&sm[0][0][0]);
    const uint32_t ARR = 128 * 24 * 2;

    float acc[2][8][4];
#pragma unroll
    for (int mt = 0; mt < 2; mt++)
#pragma unroll
        for (int nt = 0; nt < 8; nt++)
#pragma unroll
            for (int j = 0; j < 4; j++) acc[mt][nt][j] = 0.f;

    for (int kt = 0; kt < NT; kt++) {
        const int cur = kt & 1;
        if (kt + 1 < NT) {
            const int nx = cur ^ 1;
            const long kb = (long)(kt + 1) << 4;
            cp16(&sm[nx][0][soff], Ah + aoff + kb);
            cp16(&sm[nx][1][soff], Al + aoff + kb);
            cp16(&sm[nx][2][soff], Bh + boff + kb);
            cp16(&sm[nx][3][soff], Bl + boff + kb);
            cp_commit();
            cp_wait<1>();
        } else {
            cp_wait<0>();
        }
        __syncthreads();

        const uint32_t bAh = smbase + (cur * 4 + 0) * ARR;
        const uint32_t bAl = smbase + (cur * 4 + 1) * ARR;
        const uint32_t bBh = smbase + (cur * 4 + 2) * ARR;
        const uint32_t bBl = smbase + (cur * 4 + 3) * ARR;

        uint32_t ah[2][4], al[2][4], bh[4][4], bl[4][4];
#pragma unroll
        for (int mt = 0; mt < 2; mt++) {
            ldsm4(ah[mt], bAh + aoffs[mt]);
            ldsm4(al[mt], bAl + aoffs[mt]);
        }
#pragma unroll
        for (int p = 0; p < 4; p++) {
            ldsm4(bh[p], bBh + boffs[p]);
            ldsm4(bl[p], bBl + boffs[p]);
        }

#pragma unroll
        for (int mt = 0; mt < 2; mt++)
#pragma unroll
            for (int nt = 0; nt < 8; nt++)
                mma_bf(acc[mt][nt], ah[mt],
                       bh[nt >> 1][(nt & 1) * 2], bh[nt >> 1][(nt & 1) * 2 + 1]);
#pragma unroll
        for (int mt = 0; mt < 2; mt++)
#pragma unroll
            for (int nt = 0; nt < 8; nt++)
                mma_bf(acc[mt][nt], ah[mt],
                       bl[nt >> 1][(nt & 1) * 2], bl[nt >> 1][(nt & 1) * 2 + 1]);
#pragma unroll
        for (int mt = 0; mt < 2; mt++)
#pragma unroll
            for (int nt = 0; nt < 8; nt++)
                mma_bf(acc[mt][nt], al[mt],
                       bh[nt >> 1][(nt & 1) * 2], bh[nt >> 1][(nt & 1) * 2 + 1]);
        __syncthreads();
    }

#pragma unroll
    for (int mt = 0; mt < 2; mt++) {
        int r0 = m0 + wm + mt * 16 + (lane >> 2);
#pragma unroll
        for (int nt = 0; nt < 8; nt++) {
            int cc = n0 + wn + nt * 8 + (lane & 3) * 2;
            float* c = acc[mt][nt];
            if (r0 < M) {
                float2 o; o.x = c[0]; o.y = c[1];
                *(float2*)(P + (long)r0 * N + cc) = o;
            }
            if (r0 + 8 < M) {
                float2 o; o.x = c[2]; o.y = c[3];
                *(float2*)(P + (long)(r0 + 8) * N + cc) = o;
            }
        }
    }
}

// ---------------- kv reduce ----------------
__global__ void kvred_kernel(const float* __restrict__ P, const float* __restrict__ bias,
                             float* __restrict__ out) {
    int i4 = blockIdx.x * 256 + threadIdx.x;
    if (i4 >= 65536) return;
    const float4* P4 = (const float4*)P;
    float4 a = P4[i4];
#pragma unroll
    for (int s = 1; s < 8; s++) {
        float4 b = P4[s * 65536 + i4];
        a.x += b.x; a.y += b.y; a.z += b.z; a.w += b.w;
    }
    int n = (i4 * 4) & 4095;
    const float4 bv = *(const float4*)(bias + n);
    a.x += bv.x; a.y += bv.y; a.z += bv.z; a.w += bv.w;
    ((float4*)out)[i4] = a;
}

// ---------------- compete logits: cw staged in dynamic smem ----------------
__global__ void compete_kernel(const float* __restrict__ x, const float* __restrict__ cw,
                               const float* __restrict__ cb, const float* __restrict__ npw,
                               float* __restrict__ logits) {
    extern __shared__ float scw[];
    int tid = threadIdx.x;
    for (int e = tid; e < SS * DD; e += 512) scw[e] = cw[e];
    __syncthreads();
    int warp = tid >> 5, lane = tid & 31;
#pragma unroll
    for (int r = 0; r < 2; r++) {
        int row = blockIdx.x * 32 + warp * 2 + r;
        const float* xr = x + (long)row * DD;
        float ss = 0.f;
        float acc[SS];
#pragma unroll
        for (int s = 0; s < SS; s++) acc[s] = 0.f;
        for (int j = lane; j < DD; j += 32) {
            float xv = xr[j];
            ss += xv * xv;
            float xn = xv * npw[j];
#pragma unroll
            for (int s = 0; s < SS; s++) acc[s] += xn * scw[s * DD + j];
        }
#pragma unroll
        for (int o = 16; o; o >>= 1) ss += __shfl_xor_sync(0xffffffffu, ss, o);
#pragma unroll
        for (int s = 0; s < SS; s++) {
#pragma unroll
            for (int o = 16; o; o >>= 1) acc[s] += __shfl_xor_sync(0xffffffffu, acc[s], o);
        }
        float rinv = rsqrtf(ss * (1.f / DD) + EPSF);
        float myv = 0.f;
#pragma unroll
        for (int s = 0; s < SS; s++) if (lane == s) myv = acc[s];
        if (lane < SS) logits[(long)row * SS + lane] = myv * rinv + cb[lane];
    }
}

// ---------------- top-4 + softmax weights (tree merge) ----------------
__device__ __forceinline__ bool tk_better(float v1, int i1, float v2, int i2) {
    return (v1 > v2) || (v1 == v2 && i1 < i2);
}
__device__ __forceinline__ void tk_insert(float* v, int* id, float nv, int ni) {
    if (tk_better(nv, ni, v[KK - 1], id[KK - 1])) {
        v[KK - 1] = nv; id[KK - 1] = ni;
#pragma unroll
        for (int j = KK - 1; j > 0; j--) {
            if (tk_better(v[j], id[j], v[j - 1], id[j - 1])) {
                float tv = v[j]; v[j] = v[j - 1]; v[j - 1] = tv;
                int ti = id[j]; id[j] = id[j - 1]; id[j - 1] = ti;
            }
        }
    }
}

__global__ void topk_kernel(const float* __restrict__ logits, int* __restrict__ idxo,
                            float* __restrict__ wgto) {
    int bs = blockIdx.x;
    int b = bs / SS, s = bs % SS;
    int tid = threadIdx.x;
    float v[KK]; int id[KK];
#pragma unroll
    for (int k = 0; k < KK; k++) { v[k] = -3.4e38f; id[k] = 0x7fffffff; }
    for (int l = tid; l < LL; l += 256)
        tk_insert(v, id, logits[((long)b * LL + l) * SS + s], l);

    __shared__ float sv[256 * KK];
    __shared__ int   si[256 * KK];
#pragma unroll
    for (int k = 0; k < KK; k++) { sv[tid * KK + k] = v[k]; si[tid * KK + k] = id[k]; }

    for (int step = 128; step >= 1; step >>= 1) {
        __syncthreads();
        if (tid < step) {
            float* av = &sv[tid * KK]; int* ai = &si[tid * KK];
            float mv[KK]; int mi[KK];
#pragma unroll
            for (int k = 0; k < KK; k++) { mv[k] = av[k]; mi[k] = ai[k]; }
#pragma unroll
            for (int k = 0; k < KK; k++)
                tk_insert(mv, mi, sv[(tid + step) * KK + k], si[(tid + step) * KK + k]);
#pragma unroll
            for (int k = 0; k < KK; k++) { av[k] = mv[k]; ai[k] = mi[k]; }
        }
    }
    __syncthreads();
    if (tid == 0) {
        float m = sv[0];
        float e[KK]; float sum = 0.f;
#pragma unroll
        for (int k = 0; k < KK; k++) { e[k] = expf(sv[k] - m); sum += e[k]; }
        float inv = 1.f / sum;
#pragma unroll
        for (int k = 0; k < KK; k++) { wgto[bs * KK + k] = e[k] * inv; idxo[bs * KK + k] = si[k]; }
    }
}

// ---------------- weighted gather -> bf16 hi/lo ----------------
__global__ void gatherw_kernel(const float* __restrict__ x, const int* __restrict__ idx,
                               const float* __restrict__ wgt,
                               __nv_bfloat16* __restrict__ xwh, __nv_bfloat16* __restrict__ xwl) {
    int bs = blockIdx.x;
    int b = bs / SS;
    const float* r0 = x + ((long)b * LL + idx[bs * KK + 0]) * DD;
    const float* r1 = x + ((long)b * LL + idx[bs * KK + 1]) * DD;
    const float* r2 = x + ((long)b * LL + idx[bs * KK + 2]) * DD;
    const float* r3 = x + ((long)b * LL + idx[bs * KK + 3]) * DD;
    float w0 = wgt[bs * KK + 0], w1 = wgt[bs * KK + 1];
    float w2 = wgt[bs * KK + 2], w3 = wgt[bs * KK + 3];
    for (int d = threadIdx.x; d < DD; d += blockDim.x) {
        float v = w0 * r0[d] + w1 * r1[d] + w2 * r2[d] + w3 * r3[d];
        __nv_bfloat16 h, lo;
        split1(v, h, lo);
        xwh[(long)bs * DD + d] = h;
        xwl[(long)bs * DD + d] = lo;
    }
}

// ---------------- ws update + rms ----------------
__global__ void ws_update_kernel(const float* __restrict__ P, const float* __restrict__ wgt,
                                 const float* __restrict__ wb, const float* __restrict__ npw,
                                 float* __restrict__ ws,
                                 __nv_bfloat16* __restrict__ wsh, __nv_bfloat16* __restrict__ wsl) {
    int bs = blockIdx.x;
    __shared__ float t[DD];
    __shared__ float red[256];
    float sumw = wgt[bs * KK + 0] + wgt[bs * KK + 1] + wgt[bs * KK + 2] + wgt[bs * KK + 3];
    const long MN = (long)BB * SS * DD;
    long rr = (long)bs * DD;
    float ssp = 0.f;
    for (int d = threadIdx.x; d < DD; d += 256) {
        float a = sumw * wb[d];
#pragma unroll
        for (int sp = 0; sp < 8; sp++) a += P[(long)sp * MN + rr + d];
        float v = ws[rr + d] + a;
        t[d] = v; ssp += v * v;
    }
    red[threadIdx.x] = ssp; __syncthreads();
    for (int st = 128; st; st >>= 1) {
        if (threadIdx.x < st) red[threadIdx.x] += red[threadIdx.x + st];
        __syncthreads();
    }
    float rinv = rsqrtf(red[0] * (1.f / DD) + EPSF);
    for (int d = threadIdx.x; d < DD; d += 256) {
        float v = t[d] * rinv * npw[d];
        ws[rr + d] = v;
        __nv_bfloat16 h, lo;
        split1(v, h, lo);
        wsh[rr + d] = h;
        wsl[rr + d] = lo;
    }
}

// ---------------- fold kk with wq: G[b,(h,s),d] -> fp16 hi/lo ----------------
__global__ __launch_bounds__(128) void gfold_kernel(const float* __restrict__ kv,
                                                    const float* __restrict__ wq,
                                                    __half* __restrict__ Gh,
                                                    __half* __restrict__ Gl) {
    int b = blockIdx.y / HH, h = blockIdx.y % HH;
    int d0 = blockIdx.x * 128;
    __shared__ float ks[SS][HD];
    __shared__ float wqs[HD][128 + 1];
    for (int e = threadIdx.x; e < SS * HD; e += 128) {
        int s = e >> 6, i = e & 63;
        ks[s][i] = kv[((long)b * SS + s) * (2 * DD) + h * HD + i];
    }
    for (int e = threadIdx.x; e < HD * 128; e += 128) {
        int i = e >> 7, c = e & 127;
        wqs[i][c] = wq[(long)(h * HD + i) * DD + d0 + c];
    }
    __syncthreads();
    int d = threadIdx.x;
    float acc[SS];
#pragma unroll
    for (int s = 0; s < SS; s++) acc[s] = 0.f;
#pragma unroll
    for (int i = 0; i < HD; i++) {
        float w = wqs[i][d];
#pragma unroll
        for (int s = 0; s < SS; s++) acc[s] += w * ks[s][i];
    }
#pragma unroll
    for (int s = 0; s < SS; s++) {
        long off = ((long)b * HH * SS + h * SS + s) * DD + d0 + d;
        __half hh, ll;
        split1h(acc[s], hh, ll);
        Gh[off] = hh;
        Gl[off] = ll;
    }
}

// ---------------- sbias[b,h,s] ----------------
__global__ void sbias_kernel(const float* __restrict__ kv, const float* __restrict__ bq,
                             float* __restrict__ sbias) {
    int bh = blockIdx.x;
    int b = bh / HH, h = bh % HH;
    int lane = threadIdx.x;
    for (int s = 0; s < SS; s++) {
        float a = 0.f;
        for (int i = lane; i < HD; i += 32)
            a += bq[h * HD + i] * kv[((long)b * SS + s) * (2 * DD) + h * HD + i];
#pragma unroll
        for (int o = 16; o; o >>= 1) a += __shfl_xor_sync(0xffffffffu, a, o);
        if (lane == 0) sbias[(long)bh * SS + s] = a;
    }
}

// ---------------- fold vv with out_proj -> voT fp16 hi/lo ----------------
__global__ __launch_bounds__(128) void vo_kernel(const float* __restrict__ kv,
                                                 const float* __restrict__ wout,
                                                 __half* __restrict__ voTh,
                                                 __half* __restrict__ voTl) {
    int b = blockIdx.y / HH, h = blockIdx.y % HH;
    int d0 = blockIdx.x * 128;
    __shared__ float vs[SS][HD];
    __shared__ float wsm[128][HD + 1];
    for (int e = threadIdx.x; e < SS * HD; e += 128) {
        int s = e >> 6, i = e & 63;
        vs[s][i] = kv[((long)b * SS + s) * (2 * DD) + DD + h * HD + i];
    }
    for (int e = threadIdx.x; e < 128 * HD; e += 128) {
        int r = e >> 6, i = e & 63;
        wsm[r][i] = wout[(long)(d0 + r) * DD + h * HD + i];
    }
    __syncthreads();
    int d = threadIdx.x;
    float acc[SS];
#pragma unroll
    for (int s = 0; s < SS; s++) acc[s] = 0.f;
#pragma unroll
    for (int i = 0; i < HD; i++) {
        float w = wsm[d][i];
#pragma unroll
        for (int s = 0; s < SS; s++) acc[s] += w * vs[s][i];
    }
    long base = ((long)b * DD + d0 + d) * (HH * SS) + h * SS;
#pragma unroll
    for (int s = 0; s < SS; s++) {
        __half hh, ll;
        split1h(acc[s], hh, ll);
        voTh[base + s] = hh;
        voTl[base + s] = ll;
    }
}

// ---------------- x = rms(x + xb) -> fp32 out + fp16, float4 ----------------
__global__ void resid_rms_kernel(const float* __restrict__ xin, const float* __restrict__ xb,
                                 const float* __restrict__ npw, float* __restrict__ xout,
                                 __half* __restrict__ xh) {
    long row = blockIdx.x;
    __shared__ float t[DD];
    __shared__ float red[256];
    const float4* a4 = (const float4*)(xin + row * DD);
    const float4* c4 = (const float4*)(xb + row * DD);
    float4* t4 = (float4*)t;
    float ssp = 0.f;
#pragma unroll
    for (int q = 0; q < 2; q++) {
        int i4 = threadIdx.x + q * 256;
        float4 a = a4[i4], c = c4[i4];
        float4 v; v.x = a.x + c.x; v.y = a.y + c.y; v.z = a.z + c.z; v.w = a.w + c.w;
        t4[i4] = v;
        ssp += v.x * v.x + v.y * v.y + v.z * v.z + v.w * v.w;
    }
    red[threadIdx.x] = ssp; __syncthreads();
    for (int st = 128; st; st >>= 1) {
        if (threadIdx.x < st) red[threadIdx.x] += red[threadIdx.x + st];
        __syncthreads();
    }
    float rinv = rsqrtf(red[0] * (1.f / DD) + EPSF);
    const float4* w4 = (const float4*)npw;
    float4* o4 = (float4*)(xout + row * DD);
    __half2* h2 = (__half2*)(xh + row * DD);
#pragma unroll
    for (int q = 0; q < 2; q++) {
        int i4 = threadIdx.x + q * 256;
        float4 v = t4[i4], w = w4[i4];
        v.x *= rinv * w.x; v.y *= rinv * w.y; v.z *= rinv * w.z; v.w *= rinv * w.w;
        o4[i4] = v;
        h2[i4 * 2]     = __halves2half2(__float2half_rn(v.x), __float2half_rn(v.y));
        h2[i4 * 2 + 1] = __halves2half2(__float2half_rn(v.z), __float2half_rn(v.w));
    }
}

// ---------------- host launch ----------------
static inline void run_split(const float* src, __nv_bfloat16* hi, __nv_bfloat16* lo, long n) {
    long n4 = n >> 2;
    split4_kernel<<<(int)((n4 + 255) / 256), 256>>>(src, hi, lo, n4);
}

#define CW_SMEM (SS * DD * 4)

extern "C" void kernel_launch(void* const* d_in, const int* in_sizes, int n_in,
                              void* d_out, int out_size) {
    const float* x_in       = (const float*)d_in[0];
    const float* workspace  = (const float*)d_in[1];
    const float* compete_w  = (const float*)d_in[2];
    const float* compete_b  = (const float*)d_in[3];
    const float* write_w    = (const float*)d_in[4];
    const float* write_b    = (const float*)d_in[5];
    const float* in_proj_w  = (const float*)d_in[6];
    const float* in_proj_b  = (const float*)d_in[7];
    const float* out_proj_w = (const float*)d_in[8];
    const float* out_proj_b = (const float*)d_in[9];
    const float* norm_pre_w  = (const float*)d_in[12];
    const float* norm_post_w = (const float*)d_in[13];

    cudaFuncSetAttribute(compete_kernel, cudaFuncAttributeMaxDynamicSharedMemorySize, CW_SMEM);

    void *p;
    float *px, *pxb, *plog, *pws, *pkv, *ppart, *pwgt, *psb;
    int *pidx;
    __nv_bfloat16 *pwkvh, *pwkvl, *pwwh, *pwwl, *pwsh, *pwsl, *pxwh, *pxwl;
    __half *pxh, *pGh, *pGl, *patth, *pvoTh, *pvoTl;
    cudaGetSymbolAddress(&p, g_x);     px   = (float*)p;
    cudaGetSymbolAddress(&p, g_xb);    pxb  = (float*)p;
    cudaGetSymbolAddress(&p, g_logits); plog = (float*)p;
    cudaGetSymbolAddress(&p, g_ws);    pws  = (float*)p;
    cudaGetSymbolAddress(&p, g_kv);    pkv  = (float*)p;
    cudaGetSymbolAddress(&p, g_part);  ppart = (float*)p;
    cudaGetSymbolAddress(&p, g_wgt);   pwgt = (float*)p;
    cudaGetSymbolAddress(&p, g_sbias); psb  = (float*)p;
    cudaGetSymbolAddress(&p, g_idx);   pidx = (int*)p;
    cudaGetSymbolAddress(&p, g_wkvh);  pwkvh = (__nv_bfloat16*)p;
    cudaGetSymbolAddress(&p, g_wkvl);  pwkvl = (__nv_bfloat16*)p;
    cudaGetSymbolAddress(&p, g_wwh);   pwwh = (__nv_bfloat16*)p;
    cudaGetSymbolAddress(&p, g_wwl);   pwwl = (__nv_bfloat16*)p;
    cudaGetSymbolAddress(&p, g_wsh);   pwsh = (__nv_bfloat16*)p;
    cudaGetSymbolAddress(&p, g_wsl);   pwsl = (__nv_bfloat16*)p;
    cudaGetSymbolAddress(&p, g_xwh);   pxwh = (__nv_bfloat16*)p;
    cudaGetSymbolAddress(&p, g_xwl);   pxwl = (__nv_bfloat16*)p;
    cudaGetSymbolAddress(&p, g_xh);    pxh  = (__half*)p;
    cudaGetSymbolAddress(&p, g_Gh);    pGh  = (__half*)p;
    cudaGetSymbolAddress(&p, g_Gl);    pGl  = (__half*)p;
    cudaGetSymbolAddress(&p, g_atth);  patth = (__half*)p;
    cudaGetSymbolAddress(&p, g_voTh);  pvoTh = (__half*)p;
    cudaGetSymbolAddress(&p, g_voTl);  pvoTl = (__half*)p;

    // init: x <- input (fp32 + fp16), ws <- broadcast(workspace)
    {
        long n4 = (long)BB * LL * DD / 4;
        copysplit_kernel<<<(int)((n4 + 255) / 256), 256>>>(x_in, px, pxh, n4);
        init_ws_kernel<<<BB * SS, 256>>>(workspace, pws);
    }
    // weight splits (once per launch); wq stays fp32 (used only in gfold)
    run_split(in_proj_w + (long)DD * DD, pwkvh, pwkvl, (long)2 * DD * DD);
    run_split(write_w, pwwh, pwwl, (long)DD * DD);

    for (int it = 0; it < NB; it++) {
        // 1. compete logits (cw in smem)
        compete_kernel<<<BB * LL / 32, 512, CW_SMEM>>>(px, compete_w, compete_b, norm_pre_w, plog);
        // 2. top-k + softmax weights (tree merge)
        topk_kernel<<<BB * SS, 256>>>(plog, pidx, pwgt);
        // 3. weighted gather: xw = sum_k wgt_k x_k (64 rows)
        gatherw_kernel<<<BB * SS, 256>>>(px, pidx, pwgt, pxwh, pxwl);
        // 4. write projection (64 x 2048 x 2048), split-K=8 -> partials
        {
            dim3 grid(DD / 128, 1, 8);
            gemm3p_kernel<<<grid, 256>>>(pxwh, pxwl, pwwh, pwwl, ppart,
                                         BB * SS, DD, DD, DD / 8);
        }
        // 5. workspace update + rms (+hi/lo), reduces partials inline
        ws_update_kernel<<<BB * SS, 256>>>(ppart, pwgt, write_b, norm_post_w, pws, pwsh, pwsl);
        // 6. kk|vv projection (64 x 4096 x 2048), split-K=8 -> partials -> reduce
        {
            dim3 grid((2 * DD) / 128, 1, 8);
            gemm3p_kernel<<<grid, 256>>>(pwsh, pwsl, pwkvh, pwkvl, ppart,
                                         BB * SS, 2 * DD, DD, DD / 8);
            kvred_kernel<<<256, 256>>>(ppart, in_proj_b + DD, pkv);
        }
        // 7. fold kk with wq -> G fp16 hi/lo ; sbias
        {
            dim3 grid(DD / 128, BB * HH, 1);
            gfold_kernel<<<grid, 128>>>(pkv, in_proj_w, pGh, pGl);
            sbias_kernel<<<BB * HH, 32>>>(pkv, in_proj_b, psb);
        }
        // 8. fold vv with out_proj -> voT fp16 hi/lo
        {
            dim3 grid(DD / 128, BB * HH, 1);
            vo_kernel<<<grid, 128>>>(pkv, out_proj_w, pvoTh, pvoTl);
        }
        // 9. scores GEMM (2-term fp16: x_h*(Gh+Gl)) + fused softmax -> att fp16
        {
            dim3 grid(HH * SS / 128, LL / 128, BB);
            gemm2s_kernel<<<grid, 256>>>(pxh, pGh, pGl, psb, patth,
                                         DD, (long)LL * DD, (long)HH * SS * DD);
        }
        // 10. x_b = att @ (voTh+voTl)^T + out_proj_b — 2-term fp16 GEMM
        {
            dim3 grid(DD / 128, LL / 128, BB);
            gemm2_kernel<<<grid, 256>>>(patth, pvoTh, pvoTl, out_proj_b, pxb,
                                        LL, DD, HH * SS,
                                        (long)LL * HH * SS, (long)DD * HH * SS,
                                        (long)LL * DD);
        }
        // 11. x = rms(x + x_b) (+fp16); last round writes d_out
        float* xdst = (it == NB - 1) ? (float*)d_out : px;
        resid_rms_kernel<<<BB * LL, 256>>>(px, pxb, norm_post_w, xdst, pxh);
    }
}

// round 17
// speedup vs baseline: 1.5316x; 1.2864x over previous
#include <cuda_runtime.h>
#include <cuda_bf16.h>
#include <cuda_fp16.h>
#include <cstdint>

// ---------------- problem constants ----------------
#define BB 4
#define LL 2048
#define DD 2048
#define SS 16
#define KK 4
#define NB 2
#define HH 32
#define HD 64
#define EPSF 1e-6f

// ---------------- device scratch (no allocs allowed) ----------------
__device__ float g_x[BB * LL * DD];
__device__ float g_xb[BB * LL * DD];
__device__ float g_logits[BB * LL * SS];
__device__ float g_ws[BB * SS * DD];
__device__ float g_kv[BB * SS * 2 * DD];
__device__ float g_part[8 * 64 * 4096];       // split-K partials
__device__ float g_wgt[BB * SS * KK];
__device__ float g_sbias[BB * HH * SS];
__device__ int   g_idx[BB * SS * KK];

// bf16 hi/lo split operands for the small split-K projections
__device__ __nv_bfloat16 g_wkvh[2 * DD * DD],  g_wkvl[2 * DD * DD];
__device__ __nv_bfloat16 g_wwh[DD * DD],       g_wwl[DD * DD];
__device__ __nv_bfloat16 g_wsh[BB * SS * DD],  g_wsl[BB * SS * DD];
__device__ __nv_bfloat16 g_xwh[BB * SS * DD],  g_xwl[BB * SS * DD];
// fp16 operands for the attention path (1-term GEMMs; fp16 11-bit mantissa,
// dropped-lo error incoherent over K — calibrated at ~5e-5 per dropped term)
__device__ __half g_xh[BB * LL * DD];
__device__ __half g_Gh[BB * HH * SS * DD];
__device__ __half g_atth[BB * LL * HH * SS];
__device__ __half g_voTh[BB * DD * HH * SS];

// ---------------- PTX helpers ----------------
__device__ __forceinline__ void cp16(void* sdst, const void* gsrc) {
    uint32_t d = (uint32_t)__cvta_generic_to_shared(sdst);
    asm volatile("cp.async.cg.shared.global [%0], [%1], 16;\n" :: "r"(d), "l"(gsrc));
}
__device__ __forceinline__ void cp_commit() { asm volatile("cp.async.commit_group;\n"); }
template <int N> __device__ __forceinline__ void cp_wait() {
    asm volatile("cp.async.wait_group %0;\n" :: "n"(N));
}
__device__ __forceinline__ void ldsm4(uint32_t* r, uint32_t saddr) {
    asm volatile("ldmatrix.sync.aligned.m8n8.x4.shared.b16 {%0,%1,%2,%3}, [%4];\n"
                 : "=r"(r[0]), "=r"(r[1]), "=r"(r[2]), "=r"(r[3]) : "r"(saddr));
}
// bf16 inputs, f32 accumulator
__device__ __forceinline__ void mma_bf(float* c, const uint32_t* a, uint32_t b0, uint32_t b1) {
    asm volatile("mma.sync.aligned.m16n8k16.row.col.f32.bf16.bf16.f32 "
                 "{%0,%1,%2,%3}, {%4,%5,%6,%7}, {%8,%9}, {%0,%1,%2,%3};\n"
                 : "+f"(c[0]), "+f"(c[1]), "+f"(c[2]), "+f"(c[3])
                 : "r"(a[0]), "r"(a[1]), "r"(a[2]), "r"(a[3]), "r"(b0), "r"(b1));
}
// fp16 inputs, f32 accumulator
__device__ __forceinline__ void mma_fp(float* c, const uint32_t* a, uint32_t b0, uint32_t b1) {
    asm volatile("mma.sync.aligned.m16n8k16.row.col.f32.f16.f16.f32 "
                 "{%0,%1,%2,%3}, {%4,%5,%6,%7}, {%8,%9}, {%0,%1,%2,%3};\n"
                 : "+f"(c[0]), "+f"(c[1]), "+f"(c[2]), "+f"(c[3])
                 : "r"(a[0]), "r"(a[1]), "r"(a[2]), "r"(a[3]), "r"(b0), "r"(b1));
}
__device__ __forceinline__ void split1(float v, __nv_bfloat16& h, __nv_bfloat16& l) {
    h = __float2bfloat16(v);
    l = __float2bfloat16(v - __bfloat162float(h));
}
__device__ __forceinline__ uint32_t smem_u32(const void* p) {
    return (uint32_t)__cvta_generic_to_shared(p);
}

// ---------------- splits ----------------
__global__ void split4_kernel(const float* __restrict__ src, __nv_bfloat16* __restrict__ hi,
                              __nv_bfloat16* __restrict__ lo, long n4) {
    long i = (long)blockIdx.x * blockDim.x + threadIdx.x;
    if (i >= n4) return;
    float4 v = ((const float4*)src)[i];
    __nv_bfloat16 h[4], l[4];
    split1(v.x, h[0], l[0]); split1(v.y, h[1], l[1]);
    split1(v.z, h[2], l[2]); split1(v.w, h[3], l[3]);
    __nv_bfloat162 ph0; ph0.x = h[0]; ph0.y = h[1];
    __nv_bfloat162 ph1; ph1.x = h[2]; ph1.y = h[3];
    __nv_bfloat162 pl0; pl0.x = l[0]; pl0.y = l[1];
    __nv_bfloat162 pl1; pl1.x = l[2]; pl1.y = l[3];
    ((__nv_bfloat162*)hi)[2 * i]     = ph0;
    ((__nv_bfloat162*)hi)[2 * i + 1] = ph1;
    ((__nv_bfloat162*)lo)[2 * i]     = pl0;
    ((__nv_bfloat162*)lo)[2 * i + 1] = pl1;
}

// x init: fp32 copy + single fp16
__global__ void copysplit_kernel(const float* __restrict__ src, float* __restrict__ dst,
                                 __half* __restrict__ hi, long n4) {
    long i = (long)blockIdx.x * blockDim.x + threadIdx.x;
    if (i >= n4) return;
    float4 v = ((const float4*)src)[i];
    ((float4*)dst)[i] = v;
    ((__half2*)hi)[2 * i]     = __halves2half2(__float2half_rn(v.x), __float2half_rn(v.y));
    ((__half2*)hi)[2 * i + 1] = __halves2half2(__float2half_rn(v.z), __float2half_rn(v.w));
}

__global__ void init_ws_kernel(const float* __restrict__ wsrc, float* __restrict__ ws) {
    int bs = blockIdx.x;
    int s = bs % SS;
    for (int d = threadIdx.x; d < DD; d += blockDim.x)
        ws[(long)bs * DD + d] = wsrc[(long)s * DD + d];
}

// ---------------- 1-term fp16 GEMM for xb: C = A @ B^T + bias ----------------
__global__ __launch_bounds__(256) void gemm1_kernel(
    const __half* __restrict__ A, const __half* __restrict__ B,
    const float* __restrict__ bias, float* __restrict__ C,
    int M, int N, int K, long bsA, long bsB, long bsC) {
    A += (long)blockIdx.z * bsA;
    B += (long)blockIdx.z * bsB;
    C += (long)blockIdx.z * bsC;

    __shared__ __align__(16) __half sm[2][2][128 * 24];

    const int tid = threadIdx.x;
    const int m0 = blockIdx.y * 128, n0 = blockIdx.x * 128;

    const int lrow = tid >> 1, lhalf = tid & 1;
    const long aoff = (long)(m0 + lrow) * K + lhalf * 8;
    const long boff = (long)(n0 + lrow) * K + lhalf * 8;
    const uint32_t soff = lrow * 24 + lhalf * 8;

    const int NT = K >> 4;

    cp16(&sm[0][0][soff], A + aoff);
    cp16(&sm[0][1][soff], B + boff);
    cp_commit();

    const int lane = tid & 31, warp = tid >> 5;
    const int wm = (warp & 3) * 32;
    const int wn = (warp >> 2) * 64;

    uint32_t a_row = wm + (lane & 7) + ((lane >> 3) & 1) * 8;
    uint32_t a_k   = (lane >> 4) * 8;
    uint32_t aoffs[2];
    aoffs[0] = ((a_row) * 24 + a_k) * 2;
    aoffs[1] = ((a_row + 16) * 24 + a_k) * 2;
    uint32_t b_row = wn + (lane & 7) + ((lane >> 4) ? 8 : 0);
    uint32_t b_k   = ((lane >> 3) & 1) * 8;
    uint32_t boffs[4];
#pragma unroll
    for (int p = 0; p < 4; p++) boffs[p] = ((b_row + p * 16) * 24 + b_k) * 2;

    const uint32_t smbase = smem_u32(&sm[0][0][0]);
    const uint32_t ARR = 128 * 24 * 2;

    float acc[2][8][4];
#pragma unroll
    for (int mt = 0; mt < 2; mt++)
#pragma unroll
        for (int nt = 0; nt < 8; nt++)
#pragma unroll
            for (int j = 0; j < 4; j++) acc[mt][nt][j] = 0.f;

    for (int kt = 0; kt < NT; kt++) {
        const int cur = kt & 1;
        if (kt + 1 < NT) {
            const int nx = cur ^ 1;
            const long kb = (long)(kt + 1) << 4;
            cp16(&sm[nx][0][soff], A + aoff + kb);
            cp16(&sm[nx][1][soff], B + boff + kb);
            cp_commit();
            cp_wait<1>();
        } else {
            cp_wait<0>();
        }
        __syncthreads();

        const uint32_t bA = smbase + (cur * 2 + 0) * ARR;
        const uint32_t bB = smbase + (cur * 2 + 1) * ARR;

        uint32_t ah[2][4], bh[4][4];
#pragma unroll
        for (int mt = 0; mt < 2; mt++) ldsm4(ah[mt], bA + aoffs[mt]);
#pragma unroll
        for (int p = 0; p < 4; p++) ldsm4(bh[p], bB + boffs[p]);

#pragma unroll
        for (int mt = 0; mt < 2; mt++)
#pragma unroll
            for (int nt = 0; nt < 8; nt++)
                mma_fp(acc[mt][nt], ah[mt],
                       bh[nt >> 1][(nt & 1) * 2], bh[nt >> 1][(nt & 1) * 2 + 1]);
        __syncthreads();
    }

#pragma unroll
    for (int mt = 0; mt < 2; mt++) {
        int r0 = m0 + wm + mt * 16 + (lane >> 2);
#pragma unroll
        for (int nt = 0; nt < 8; nt++) {
            int cc = n0 + wn + nt * 8 + (lane & 3) * 2;
            float b0v = bias[cc], b1v = bias[cc + 1];
            float* c = acc[mt][nt];
            float2 o0; o0.x = c[0] + b0v; o0.y = c[1] + b1v;
            *(float2*)(C + (long)r0 * N + cc) = o0;
            float2 o1; o1.x = c[2] + b0v; o1.y = c[3] + b1v;
            *(float2*)(C + (long)(r0 + 8) * N + cc) = o1;
        }
    }
}

// ---------------- 1-term fp16 scores GEMM + fused softmax -> fp16 att ----------------
__global__ __launch_bounds__(256) void gemm1s_kernel(
    const __half* __restrict__ A, const __half* __restrict__ B,
    const float* __restrict__ sbias,
    __half* __restrict__ atth,
    int K, long bsA, long bsB) {
    const int b = blockIdx.z;
    A += (long)b * bsA;
    B += (long)b * bsB;
    const float* sb = sbias + (long)b * (HH * SS);

    __shared__ __align__(16) __half sm[2][2][128 * 24];

    const int tid = threadIdx.x;
    const int m0 = blockIdx.y * 128, n0 = blockIdx.x * 128;

    const int lrow = tid >> 1, lhalf = tid & 1;
    const long aoff = (long)(m0 + lrow) * K + lhalf * 8;
    const long boff = (long)(n0 + lrow) * K + lhalf * 8;
    const uint32_t soff = lrow * 24 + lhalf * 8;

    const int NT = K >> 4;

    cp16(&sm[0][0][soff], A + aoff);
    cp16(&sm[0][1][soff], B + boff);
    cp_commit();

    const int lane = tid & 31, warp = tid >> 5;
    const int wm = (warp & 3) * 32;
    const int wn = (warp >> 2) * 64;

    uint32_t a_row = wm + (lane & 7) + ((lane >> 3) & 1) * 8;
    uint32_t a_k   = (lane >> 4) * 8;
    uint32_t aoffs[2];
    aoffs[0] = ((a_row) * 24 + a_k) * 2;
    aoffs[1] = ((a_row + 16) * 24 + a_k) * 2;
    uint32_t b_row = wn + (lane & 7) + ((lane >> 4) ? 8 : 0);
    uint32_t b_k   = ((lane >> 3) & 1) * 8;
    uint32_t boffs[4];
#pragma unroll
    for (int p = 0; p < 4; p++) boffs[p] = ((b_row + p * 16) * 24 + b_k) * 2;

    const uint32_t smbase = smem_u32(&sm[0][0][0]);
    const uint32_t ARR = 128 * 24 * 2;

    float acc[2][8][4];
#pragma unroll
    for (int mt = 0; mt < 2; mt++)
#pragma unroll
        for (int nt = 0; nt < 8; nt++)
#pragma unroll
            for (int j = 0; j < 4; j++) acc[mt][nt][j] = 0.f;

    for (int kt = 0; kt < NT; kt++) {
        const int cur = kt & 1;
        if (kt + 1 < NT) {
            const int nx = cur ^ 1;
            const long kb = (long)(kt + 1) << 4;
            cp16(&sm[nx][0][soff], A + aoff + kb);
            cp16(&sm[nx][1][soff], B + boff + kb);
            cp_commit();
            cp_wait<1>();
        } else {
            cp_wait<0>();
        }
        __syncthreads();

        const uint32_t bA = smbase + (cur * 2 + 0) * ARR;
        const uint32_t bB = smbase + (cur * 2 + 1) * ARR;

        uint32_t ah[2][4], bh[4][4];
#pragma unroll
        for (int mt = 0; mt < 2; mt++) ldsm4(ah[mt], bA + aoffs[mt]);
#pragma unroll
        for (int p = 0; p < 4; p++) ldsm4(bh[p], bB + boffs[p]);

#pragma unroll
        for (int mt = 0; mt < 2; mt++)
#pragma unroll
            for (int nt = 0; nt < 8; nt++)
                mma_fp(acc[mt][nt], ah[mt],
                       bh[nt >> 1][(nt & 1) * 2], bh[nt >> 1][(nt & 1) * 2 + 1]);
        __syncthreads();
    }

    // fused softmax epilogue over 16-col head groups (quad shfl) -> fp16 att
#pragma unroll
    for (int mt = 0; mt < 2; mt++) {
        int r0 = m0 + wm + mt * 16 + (lane >> 2);
#pragma unroll
        for (int half = 0; half < 2; half++) {
            int row = r0 + half * 8;
            long obase = ((long)b * LL + row) * (HH * SS) + n0;
#pragma unroll
            for (int g = 0; g < 4; g++) {
                int c0 = wn + (2 * g) * 8 + (lane & 3) * 2;
                int c1 = wn + (2 * g + 1) * 8 + (lane & 3) * 2;
                float x0 = (acc[mt][2 * g][half * 2 + 0]     + sb[n0 + c0])     * 0.125f;
                float x1 = (acc[mt][2 * g][half * 2 + 1]     + sb[n0 + c0 + 1]) * 0.125f;
                float x2 = (acc[mt][2 * g + 1][half * 2 + 0] + sb[n0 + c1])     * 0.125f;
                float x3 = (acc[mt][2 * g + 1][half * 2 + 1] + sb[n0 + c1 + 1]) * 0.125f;
                float mx = fmaxf(fmaxf(x0, x1), fmaxf(x2, x3));
                mx = fmaxf(mx, __shfl_xor_sync(0xffffffffu, mx, 1));
                mx = fmaxf(mx, __shfl_xor_sync(0xffffffffu, mx, 2));
                float e0 = expf(x0 - mx), e1 = expf(x1 - mx);
                float e2 = expf(x2 - mx), e3 = expf(x3 - mx);
                float s = e0 + e1 + e2 + e3;
                s += __shfl_xor_sync(0xffffffffu, s, 1);
                s += __shfl_xor_sync(0xffffffffu, s, 2);
                float inv = 1.f / s;
                *(__half2*)(atth + obase + c0) =
                    __halves2half2(__float2half_rn(e0 * inv), __float2half_rn(e1 * inv));
                *(__half2*)(atth + obase + c1) =
                    __halves2half2(__float2half_rn(e2 * inv), __float2half_rn(e3 * inv));
            }
        }
    }
}

// ---------------- split-K bf16x3 GEMM: partial C (no bias) ----------------
__global__ __launch_bounds__(256) void gemm3p_kernel(
    const __nv_bfloat16* __restrict__ Ah, const __nv_bfloat16* __restrict__ Al,
    const __nv_bfloat16* __restrict__ Bh, const __nv_bfloat16* __restrict__ Bl,
    float* __restrict__ P, int M, int N, int K, int kLen) {
    const int ksplit = blockIdx.z;
    const int k0base = ksplit * kLen;
    P += (long)ksplit * M * N;

    __shared__ __align__(16) __nv_bfloat16 sm[2][4][128 * 24];

    const int tid = threadIdx.x;
    const int m0 = blockIdx.y * 128, n0 = blockIdx.x * 128;

    const int lrow = tid >> 1, lhalf = tid & 1;
    int arow = m0 + lrow; if (arow >= M) arow = M - 1;
    int brow = n0 + lrow; if (brow >= N) brow = N - 1;
    const long aoff = (long)arow * K + k0base + lhalf * 8;
    const long boff = (long)brow * K + k0base + lhalf * 8;
    const uint32_t soff = lrow * 24 + lhalf * 8;

    const int NT = kLen >> 4;

    cp16(&sm[0][0][soff], Ah + aoff);
    cp16(&sm[0][1][soff], Al + aoff);
    cp16(&sm[0][2][soff], Bh + boff);
    cp16(&sm[0][3][soff], Bl + boff);
    cp_commit();

    const int lane = tid & 31, warp = tid >> 5;
    const int wm = (warp & 3) * 32;
    const int wn = (warp >> 2) * 64;

    uint32_t a_row = wm + (lane & 7) + ((lane >> 3) & 1) * 8;
    uint32_t a_k   = (lane >> 4) * 8;
    uint32_t aoffs[2];
    aoffs[0] = ((a_row) * 24 + a_k) * 2;
    aoffs[1] = ((a_row + 16) * 24 + a_k) * 2;
    uint32_t b_row = wn + (lane & 7) + ((lane >> 4) ? 8 : 0);
    uint32_t b_k   = ((lane >> 3) & 1) * 8;
    uint32_t boffs[4];
#pragma unroll
    for (int p = 0; p < 4; p++) boffs[p] = ((b_row + p * 16) * 24 + b_k) * 2;

    const uint32_t smbase = smem_u32(&sm[0][0][0]);
    const uint32_t ARR = 128 * 24 * 2;

    float acc[2][8][4];
#pragma unroll
    for (int mt = 0; mt < 2; mt++)
#pragma unroll
        for (int nt = 0; nt < 8; nt++)
#pragma unroll
            for (int j = 0; j < 4; j++) acc[mt][nt][j] = 0.f;

    for (int kt = 0; kt < NT; kt++) {
        const int cur = kt & 1;
        if (kt + 1 < NT) {
            const int nx = cur ^ 1;
            const long kb = (long)(kt + 1) << 4;
            cp16(&sm[nx][0][soff], Ah + aoff + kb);
            cp16(&sm[nx][1][soff], Al + aoff + kb);
            cp16(&sm[nx][2][soff], Bh + boff + kb);
            cp16(&sm[nx][3][soff], Bl + boff + kb);
            cp_commit();
            cp_wait<1>();
        } else {
            cp_wait<0>();
        }
        __syncthreads();

        const uint32_t bAh = smbase + (cur * 4 + 0) * ARR;
        const uint32_t bAl = smbase + (cur * 4 + 1) * ARR;
        const uint32_t bBh = smbase + (cur * 4 + 2) * ARR;
        const uint32_t bBl = smbase + (cur * 4 + 3) * ARR;

        uint32_t ah[2][4], al[2][4], bh[4][4], bl[4][4];
#pragma unroll
        for (int mt = 0; mt < 2; mt++) {
            ldsm4(ah[mt], bAh + aoffs[mt]);
            ldsm4(al[mt], bAl + aoffs[mt]);
        }
#pragma unroll
        for (int p = 0; p < 4; p++) {
            ldsm4(bh[p], bBh + boffs[p]);
            ldsm4(bl[p], bBl + boffs[p]);
        }

#pragma unroll
        for (int mt = 0; mt < 2; mt++)
#pragma unroll
            for (int nt = 0; nt < 8; nt++)
                mma_bf(acc[mt][nt], ah[mt],
                       bh[nt >> 1][(nt & 1) * 2], bh[nt >> 1][(nt & 1) * 2 + 1]);
#pragma unroll
        for (int mt = 0; mt < 2; mt++)
#pragma unroll
            for (int nt = 0; nt < 8; nt++)
                mma_bf(acc[mt][nt], ah[mt],
                       bl[nt >> 1][(nt & 1) * 2], bl[nt >> 1][(nt & 1) * 2 + 1]);
#pragma unroll
        for (int mt = 0; mt < 2; mt++)
#pragma unroll
            for (int nt = 0; nt < 8; nt++)
                mma_bf(acc[mt][nt], al[mt],
                       bh[nt >> 1][(nt & 1) * 2], bh[nt >> 1][(nt & 1) * 2 + 1]);
        __syncthreads();
    }

#pragma unroll
    for (int mt = 0; mt < 2; mt++) {
        int r0 = m0 + wm + mt * 16 + (lane >> 2);
#pragma unroll
        for (int nt = 0; nt < 8; nt++) {
            int cc = n0 + wn + nt * 8 + (lane & 3) * 2;
            float* c = acc[mt][nt];
            if (r0 < M) {
                float2 o; o.x = c[0]; o.y = c[1];
                *(float2*)(P + (long)r0 * N + cc) = o;
            }
            if (r0 + 8 < M) {
                float2 o; o.x = c[2]; o.y = c[3];
                *(float2*)(P + (long)(r0 + 8) * N + cc) = o;
            }
        }
    }
}

// ---------------- kv reduce ----------------
__global__ void kvred_kernel(const float* __restrict__ P, const float* __restrict__ bias,
                             float* __restrict__ out) {
    int i4 = blockIdx.x * 256 + threadIdx.x;
    if (i4 >= 65536) return;
    const float4* P4 = (const float4*)P;
    float4 a = P4[i4];
#pragma unroll
    for (int s = 1; s < 8; s++) {
        float4 b = P4[s * 65536 + i4];
        a.x += b.x; a.y += b.y; a.z += b.z; a.w += b.w;
    }
    int n = (i4 * 4) & 4095;
    const float4 bv = *(const float4*)(bias + n);
    a.x += bv.x; a.y += bv.y; a.z += bv.z; a.w += bv.w;
    ((float4*)out)[i4] = a;
}

// ---------------- compete logits: cw staged in dynamic smem ----------------
__global__ void compete_kernel(const float* __restrict__ x, const float* __restrict__ cw,
                               const float* __restrict__ cb, const float* __restrict__ npw,
                               float* __restrict__ logits) {
    extern __shared__ float scw[];
    int tid = threadIdx.x;
    for (int e = tid; e < SS * DD; e += 512) scw[e] = cw[e];
    __syncthreads();
    int warp = tid >> 5, lane = tid & 31;
#pragma unroll
    for (int r = 0; r < 2; r++) {
        int row = blockIdx.x * 32 + warp * 2 + r;
        const float* xr = x + (long)row * DD;
        float ss = 0.f;
        float acc[SS];
#pragma unroll
        for (int s = 0; s < SS; s++) acc[s] = 0.f;
        for (int j = lane; j < DD; j += 32) {
            float xv = xr[j];
            ss += xv * xv;
            float xn = xv * npw[j];
#pragma unroll
            for (int s = 0; s < SS; s++) acc[s] += xn * scw[s * DD + j];
        }
#pragma unroll
        for (int o = 16; o; o >>= 1) ss += __shfl_xor_sync(0xffffffffu, ss, o);
#pragma unroll
        for (int s = 0; s < SS; s++) {
#pragma unroll
            for (int o = 16; o; o >>= 1) acc[s] += __shfl_xor_sync(0xffffffffu, acc[s], o);
        }
        float rinv = rsqrtf(ss * (1.f / DD) + EPSF);
        float myv = 0.f;
#pragma unroll
        for (int s = 0; s < SS; s++) if (lane == s) myv = acc[s];
        if (lane < SS) logits[(long)row * SS + lane] = myv * rinv + cb[lane];
    }
}

// ---------------- top-4 + softmax weights (tree merge) ----------------
__device__ __forceinline__ bool tk_better(float v1, int i1, float v2, int i2) {
    return (v1 > v2) || (v1 == v2 && i1 < i2);
}
__device__ __forceinline__ void tk_insert(float* v, int* id, float nv, int ni) {
    if (tk_better(nv, ni, v[KK - 1], id[KK - 1])) {
        v[KK - 1] = nv; id[KK - 1] = ni;
#pragma unroll
        for (int j = KK - 1; j > 0; j--) {
            if (tk_better(v[j], id[j], v[j - 1], id[j - 1])) {
                float tv = v[j]; v[j] = v[j - 1]; v[j - 1] = tv;
                int ti = id[j]; id[j] = id[j - 1]; id[j - 1] = ti;
            }
        }
    }
}

__global__ void topk_kernel(const float* __restrict__ logits, int* __restrict__ idxo,
                            float* __restrict__ wgto) {
    int bs = blockIdx.x;
    int b = bs / SS, s = bs % SS;
    int tid = threadIdx.x;
    float v[KK]; int id[KK];
#pragma unroll
    for (int k = 0; k < KK; k++) { v[k] = -3.4e38f; id[k] = 0x7fffffff; }
    for (int l = tid; l < LL; l += 256)
        tk_insert(v, id, logits[((long)b * LL + l) * SS + s], l);

    __shared__ float sv[256 * KK];
    __shared__ int   si[256 * KK];
#pragma unroll
    for (int k = 0; k < KK; k++) { sv[tid * KK + k] = v[k]; si[tid * KK + k] = id[k]; }

    for (int step = 128; step >= 1; step >>= 1) {
        __syncthreads();
        if (tid < step) {
            float* av = &sv[tid * KK]; int* ai = &si[tid * KK];
            float mv[KK]; int mi[KK];
#pragma unroll
            for (int k = 0; k < KK; k++) { mv[k] = av[k]; mi[k] = ai[k]; }
#pragma unroll
            for (int k = 0; k < KK; k++)
                tk_insert(mv, mi, sv[(tid + step) * KK + k], si[(tid + step) * KK + k]);
#pragma unroll
            for (int k = 0; k < KK; k++) { av[k] = mv[k]; ai[k] = mi[k]; }
        }
    }
    __syncthreads();
    if (tid == 0) {
        float m = sv[0];
        float e[KK]; float sum = 0.f;
#pragma unroll
        for (int k = 0; k < KK; k++) { e[k] = expf(sv[k] - m); sum += e[k]; }
        float inv = 1.f / sum;
#pragma unroll
        for (int k = 0; k < KK; k++) { wgto[bs * KK + k] = e[k] * inv; idxo[bs * KK + k] = si[k]; }
    }
}

// ---------------- weighted gather -> bf16 hi/lo ----------------
__global__ void gatherw_kernel(const float* __restrict__ x, const int* __restrict__ idx,
                               const float* __restrict__ wgt,
                               __nv_bfloat16* __restrict__ xwh, __nv_bfloat16* __restrict__ xwl) {
    int bs = blockIdx.x;
    int b = bs / SS;
    const float* r0 = x + ((long)b * LL + idx[bs * KK + 0]) * DD;
    const float* r1 = x + ((long)b * LL + idx[bs * KK + 1]) * DD;
    const float* r2 = x + ((long)b * LL + idx[bs * KK + 2]) * DD;
    const float* r3 = x + ((long)b * LL + idx[bs * KK + 3]) * DD;
    float w0 = wgt[bs * KK + 0], w1 = wgt[bs * KK + 1];
    float w2 = wgt[bs * KK + 2], w3 = wgt[bs * KK + 3];
    for (int d = threadIdx.x; d < DD; d += blockDim.x) {
        float v = w0 * r0[d] + w1 * r1[d] + w2 * r2[d] + w3 * r3[d];
        __nv_bfloat16 h, lo;
        split1(v, h, lo);
        xwh[(long)bs * DD + d] = h;
        xwl[(long)bs * DD + d] = lo;
    }
}

// ---------------- ws update + rms ----------------
__global__ void ws_update_kernel(const float* __restrict__ P, const float* __restrict__ wgt,
                                 const float* __restrict__ wb, const float* __restrict__ npw,
                                 float* __restrict__ ws,
                                 __nv_bfloat16* __restrict__ wsh, __nv_bfloat16* __restrict__ wsl) {
    int bs = blockIdx.x;
    __shared__ float t[DD];
    __shared__ float red[256];
    float sumw = wgt[bs * KK + 0] + wgt[bs * KK + 1] + wgt[bs * KK + 2] + wgt[bs * KK + 3];
    const long MN = (long)BB * SS * DD;
    long rr = (long)bs * DD;
    float ssp = 0.f;
    for (int d = threadIdx.x; d < DD; d += 256) {
        float a = sumw * wb[d];
#pragma unroll
        for (int sp = 0; sp < 8; sp++) a += P[(long)sp * MN + rr + d];
        float v = ws[rr + d] + a;
        t[d] = v; ssp += v * v;
    }
    red[threadIdx.x] = ssp; __syncthreads();
    for (int st = 128; st; st >>= 1) {
        if (threadIdx.x < st) red[threadIdx.x] += red[threadIdx.x + st];
        __syncthreads();
    }
    float rinv = rsqrtf(red[0] * (1.f / DD) + EPSF);
    for (int d = threadIdx.x; d < DD; d += 256) {
        float v = t[d] * rinv * npw[d];
        ws[rr + d] = v;
        __nv_bfloat16 h, lo;
        split1(v, h, lo);
        wsh[rr + d] = h;
        wsl[rr + d] = lo;
    }
}

// ---------------- fold kk with wq: G[b,(h,s),d] -> fp16 ----------------
__global__ __launch_bounds__(128) void gfold_kernel(const float* __restrict__ kv,
                                                    const float* __restrict__ wq,
                                                    __half* __restrict__ Gh) {
    int b = blockIdx.y / HH, h = blockIdx.y % HH;
    int d0 = blockIdx.x * 128;
    __shared__ float ks[SS][HD];
    __shared__ float wqs[HD][128 + 1];
    for (int e = threadIdx.x; e < SS * HD; e += 128) {
        int s = e >> 6, i = e & 63;
        ks[s][i] = kv[((long)b * SS + s) * (2 * DD) + h * HD + i];
    }
    for (int e = threadIdx.x; e < HD * 128; e += 128) {
        int i = e >> 7, c = e & 127;
        wqs[i][c] = wq[(long)(h * HD + i) * DD + d0 + c];
    }
    __syncthreads();
    int d = threadIdx.x;
    float acc[SS];
#pragma unroll
    for (int s = 0; s < SS; s++) acc[s] = 0.f;
#pragma unroll
    for (int i = 0; i < HD; i++) {
        float w = wqs[i][d];
#pragma unroll
        for (int s = 0; s < SS; s++) acc[s] += w * ks[s][i];
    }
#pragma unroll
    for (int s = 0; s < SS; s++) {
        long off = ((long)b * HH * SS + h * SS + s) * DD + d0 + d;
        Gh[off] = __float2half_rn(acc[s]);
    }
}

// ---------------- sbias[b,h,s] ----------------
__global__ void sbias_kernel(const float* __restrict__ kv, const float* __restrict__ bq,
                             float* __restrict__ sbias) {
    int bh = blockIdx.x;
    int b = bh / HH, h = bh % HH;
    int lane = threadIdx.x;
    for (int s = 0; s < SS; s++) {
        float a = 0.f;
        for (int i = lane; i < HD; i += 32)
            a += bq[h * HD + i] * kv[((long)b * SS + s) * (2 * DD) + h * HD + i];
#pragma unroll
        for (int o = 16; o; o >>= 1) a += __shfl_xor_sync(0xffffffffu, a, o);
        if (lane == 0) sbias[(long)bh * SS + s] = a;
    }
}

// ---------------- fold vv with out_proj -> voT fp16 ----------------
__global__ __launch_bounds__(128) void vo_kernel(const float* __restrict__ kv,
                                                 const float* __restrict__ wout,
                                                 __half* __restrict__ voTh) {
    int b = blockIdx.y / HH, h = blockIdx.y % HH;
    int d0 = blockIdx.x * 128;
    __shared__ float vs[SS][HD];
    __shared__ float wsm[128][HD + 1];
    for (int e = threadIdx.x; e < SS * HD; e += 128) {
        int s = e >> 6, i = e & 63;
        vs[s][i] = kv[((long)b * SS + s) * (2 * DD) + DD + h * HD + i];
    }
    for (int e = threadIdx.x; e < 128 * HD; e += 128) {
        int r = e >> 6, i = e & 63;
        wsm[r][i] = wout[(long)(d0 + r) * DD + h * HD + i];
    }
    __syncthreads();
    int d = threadIdx.x;
    float acc[SS];
#pragma unroll
    for (int s = 0; s < SS; s++) acc[s] = 0.f;
#pragma unroll
    for (int i = 0; i < HD; i++) {
        float w = wsm[d][i];
#pragma unroll
        for (int s = 0; s < SS; s++) acc[s] += w * vs[s][i];
    }
    long base = ((long)b * DD + d0 + d) * (HH * SS) + h * SS;
#pragma unroll
    for (int s = 0; s < SS; s++)
        voTh[base + s] = __float2half_rn(acc[s]);
}

// ---------------- x = rms(x + xb) -> fp32 out + fp16, float4 ----------------
__global__ void resid_rms_kernel(const float* __restrict__ xin, const float* __restrict__ xb,
                                 const float* __restrict__ npw, float* __restrict__ xout,
                                 __half* __restrict__ xh) {
    long row = blockIdx.x;
    __shared__ float t[DD];
    __shared__ float red[256];
    const float4* a4 = (const float4*)(xin + row * DD);
    const float4* c4 = (const float4*)(xb + row * DD);
    float4* t4 = (float4*)t;
    float ssp = 0.f;
#pragma unroll
    for (int q = 0; q < 2; q++) {
        int i4 = threadIdx.x + q * 256;
        float4 a = a4[i4], c = c4[i4];
        float4 v; v.x = a.x + c.x; v.y = a.y + c.y; v.z = a.z + c.z; v.w = a.w + c.w;
        t4[i4] = v;
        ssp += v.x * v.x + v.y * v.y + v.z * v.z + v.w * v.w;
    }
    red[threadIdx.x] = ssp; __syncthreads();
    for (int st = 128; st; st >>= 1) {
        if (threadIdx.x < st) red[threadIdx.x] += red[threadIdx.x + st];
        __syncthreads();
    }
    float rinv = rsqrtf(red[0] * (1.f / DD) + EPSF);
    const float4* w4 = (const float4*)npw;
    float4* o4 = (float4*)(xout + row * DD);
    __half2* h2 = (__half2*)(xh + row * DD);
#pragma unroll
    for (int q = 0; q < 2; q++) {
        int i4 = threadIdx.x + q * 256;
        float4 v = t4[i4], w = w4[i4];
        v.x *= rinv * w.x; v.y *= rinv * w.y; v.z *= rinv * w.z; v.w *= rinv * w.w;
        o4[i4] = v;
        h2[i4 * 2]     = __halves2half2(__float2half_rn(v.x), __float2half_rn(v.y));
        h2[i4 * 2 + 1] = __halves2half2(__float2half_rn(v.z), __float2half_rn(v.w));
    }
}

// ---------------- host launch ----------------
static inline void run_split(const float* src, __nv_bfloat16* hi, __nv_bfloat16* lo, long n) {
    long n4 = n >> 2;
    split4_kernel<<<(int)((n4 + 255) / 256), 256>>>(src, hi, lo, n4);
}

#define CW_SMEM (SS * DD * 4)

extern "C" void kernel_launch(void* const* d_in, const int* in_sizes, int n_in,
                              void* d_out, int out_size) {
    const float* x_in       = (const float*)d_in[0];
    const float* workspace  = (const float*)d_in[1];
    const float* compete_w  = (const float*)d_in[2];
    const float* compete_b  = (const float*)d_in[3];
    const float* write_w    = (const float*)d_in[4];
    const float* write_b    = (const float*)d_in[5];
    const float* in_proj_w  = (const float*)d_in[6];
    const float* in_proj_b  = (const float*)d_in[7];
    const float* out_proj_w = (const float*)d_in[8];
    const float* out_proj_b = (const float*)d_in[9];
    const float* norm_pre_w  = (const float*)d_in[12];
    const float* norm_post_w = (const float*)d_in[13];

    cudaFuncSetAttribute(compete_kernel, cudaFuncAttributeMaxDynamicSharedMemorySize, CW_SMEM);

    void *p;
    float *px, *pxb, *plog, *pws, *pkv, *ppart, *pwgt, *psb;
    int *pidx;
    __nv_bfloat16 *pwkvh, *pwkvl, *pwwh, *pwwl, *pwsh, *pwsl, *pxwh, *pxwl;
    __half *pxh, *pGh, *patth, *pvoTh;
    cudaGetSymbolAddress(&p, g_x);     px   = (float*)p;
    cudaGetSymbolAddress(&p, g_xb);    pxb  = (float*)p;
    cudaGetSymbolAddress(&p, g_logits); plog = (float*)p;
    cudaGetSymbolAddress(&p, g_ws);    pws  = (float*)p;
    cudaGetSymbolAddress(&p, g_kv);    pkv  = (float*)p;
    cudaGetSymbolAddress(&p, g_part);  ppart = (float*)p;
    cudaGetSymbolAddress(&p, g_wgt);   pwgt = (float*)p;
    cudaGetSymbolAddress(&p, g_sbias); psb  = (float*)p;
    cudaGetSymbolAddress(&p, g_idx);   pidx = (int*)p;
    cudaGetSymbolAddress(&p, g_wkvh);  pwkvh = (__nv_bfloat16*)p;
    cudaGetSymbolAddress(&p, g_wkvl);  pwkvl = (__nv_bfloat16*)p;
    cudaGetSymbolAddress(&p, g_wwh);   pwwh = (__nv_bfloat16*)p;
    cudaGetSymbolAddress(&p, g_wwl);   pwwl = (__nv_bfloat16*)p;
    cudaGetSymbolAddress(&p, g_wsh);   pwsh = (__nv_bfloat16*)p;
    cudaGetSymbolAddress(&p, g_wsl);   pwsl = (__nv_bfloat16*)p;
    cudaGetSymbolAddress(&p, g_xwh);   pxwh = (__nv_bfloat16*)p;
    cudaGetSymbolAddress(&p, g_xwl);   pxwl = (__nv_bfloat16*)p;
    cudaGetSymbolAddress(&p, g_xh);    pxh  = (__half*)p;
    cudaGetSymbolAddress(&p, g_Gh);    pGh  = (__half*)p;
    cudaGetSymbolAddress(&p, g_atth);  patth = (__half*)p;
    cudaGetSymbolAddress(&p, g_voTh);  pvoTh = (__half*)p;

    // init: x <- input (fp32 + fp16), ws <- broadcast(workspace)
    {
        long n4 = (long)BB * LL * DD / 4;
        copysplit_kernel<<<(int)((n4 + 255) / 256), 256>>>(x_in, px, pxh, n4);
        init_ws_kernel<<<BB * SS, 256>>>(workspace, pws);
    }
    // weight splits (once per launch); wq stays fp32 (used only in gfold)
    run_split(in_proj_w + (long)DD * DD, pwkvh, pwkvl, (long)2 * DD * DD);
    run_split(write_w, pwwh, pwwl, (long)DD * DD);

    for (int it = 0; it < NB; it++) {
        // 1. compete logits (cw in smem)
        compete_kernel<<<BB * LL / 32, 512, CW_SMEM>>>(px, compete_w, compete_b, norm_pre_w, plog);
        // 2. top-k + softmax weights (tree merge)
        topk_kernel<<<BB * SS, 256>>>(plog, pidx, pwgt);
        // 3. weighted gather: xw = sum_k wgt_k x_k (64 rows)
        gatherw_kernel<<<BB * SS, 256>>>(px, pidx, pwgt, pxwh, pxwl);
        // 4. write projection (64 x 2048 x 2048), split-K=8 -> partials
        {
            dim3 grid(DD / 128, 1, 8);
            gemm3p_kernel<<<grid, 256>>>(pxwh, pxwl, pwwh, pwwl, ppart,
                                         BB * SS, DD, DD, DD / 8);
        }
        // 5. workspace update + rms (+hi/lo), reduces partials inline
        ws_update_kernel<<<BB * SS, 256>>>(ppart, pwgt, write_b, norm_post_w, pws, pwsh, pwsl);
        // 6. kk|vv projection (64 x 4096 x 2048), split-K=8 -> partials -> reduce
        {
            dim3 grid((2 * DD) / 128, 1, 8);
            gemm3p_kernel<<<grid, 256>>>(pwsh, pwsl, pwkvh, pwkvl, ppart,
                                         BB * SS, 2 * DD, DD, DD / 8);
            kvred_kernel<<<256, 256>>>(ppart, in_proj_b + DD, pkv);
        }
        // 7. fold kk with wq -> G fp16 ; sbias
        {
            dim3 grid(DD / 128, BB * HH, 1);
            gfold_kernel<<<grid, 128>>>(pkv, in_proj_w, pGh);
            sbias_kernel<<<BB * HH, 32>>>(pkv, in_proj_b, psb);
        }
        // 8. fold vv with out_proj -> voT fp16
        {
            dim3 grid(DD / 128, BB * HH, 1);
            vo_kernel<<<grid, 128>>>(pkv, out_proj_w, pvoTh);
        }
        // 9. scores GEMM (1-term fp16) + fused softmax -> att fp16
        {
            dim3 grid(HH * SS / 128, LL / 128, BB);
            gemm1s_kernel<<<grid, 256>>>(pxh, pGh, psb, patth,
                                         DD, (long)LL * DD, (long)HH * SS * DD);
        }
        // 10. x_b = att @ voT^T + out_proj_b — 1-term fp16 GEMM
        {
            dim3 grid(DD / 128, LL / 128, BB);
            gemm1_kernel<<<grid, 256>>>(patth, pvoTh, out_proj_b, pxb,
                                        LL, DD, HH * SS,
                                        (long)LL * HH * SS, (long)DD * HH * SS,
                                        (long)LL * DD);
        }
        // 11. x = rms(x + x_b) (+fp16); last round writes d_out
        float* xdst = (it == NB - 1) ? (float*)d_out : px;
        resid_rms_kernel<<<BB * LL, 256>>>(px, pxb, norm_post_w, xdst, pxh);
    }
}